// round 1
// baseline (speedup 1.0000x reference)
#include <cuda_runtime.h>
#include <math.h>

#define B_ 8
#define N_ 1024
#define DIN 512
#define C_ 256
#define T_ 8192
#define K_ 31
#define L_ 3
#define EPS_ 1e-5f

// scratch (allocation-free rule: device globals)
__device__ float g_x[B_ * T_ * C_];   // 64 MB
__device__ float g_h[B_ * T_ * C_];   // 64 MB
__device__ int   g_idx[B_ * T_];

// ---------------------------------------------------------------------------
// Kernel 1: frame -> phoneme index via duration cumsum + binary search
// ---------------------------------------------------------------------------
__global__ void idx_kernel(const int* __restrict__ durations) {
    __shared__ int cum[N_];
    int b = blockIdx.x;
    for (int n = threadIdx.x; n < N_; n += blockDim.x)
        cum[n] = durations[b * N_ + n];
    __syncthreads();
    if (threadIdx.x == 0) {
        int s = 0;
        for (int n = 0; n < N_; n++) { s += cum[n]; cum[n] = s; }
    }
    __syncthreads();
    for (int t = threadIdx.x; t < T_; t += blockDim.x) {
        int lo = 0, hi = N_ - 1;
        while (lo < hi) {
            int mid = (lo + hi) >> 1;
            if (cum[mid] > t) hi = mid; else lo = mid + 1;
        }
        g_idx[b * T_ + t] = lo;
    }
}

// ---------------------------------------------------------------------------
// Kernel 2: fused upsample-gather + in_proj + sinusoidal pos-emb proj
//   x[b,t,c] = pooled[b,idx,:]@W_in[:,c] + b_in[c] + pos(rel)@W_pos[:,c] + b_pos[c]
// One block = 8 frames, 256 threads (one per output channel).
// ---------------------------------------------------------------------------
#define FR 8
__global__ __launch_bounds__(256) void inproj_kernel(
    const float* __restrict__ pooled, const float* __restrict__ rel_pos,
    const float* __restrict__ W_in, const float* __restrict__ b_in,
    const float* __restrict__ W_pos, const float* __restrict__ b_pos)
{
    __shared__ float sh_in[FR * DIN];    // 16 KB
    __shared__ float sh_pos[FR * C_];    // 8 KB
    __shared__ int   sh_id[FR];

    int c  = threadIdx.x;
    int b  = blockIdx.y;
    int t0 = blockIdx.x * FR;

    if (c < FR) sh_id[c] = g_idx[b * T_ + t0 + c];
    __syncthreads();

    for (int u = c; u < FR * DIN; u += 256) {
        int f = u >> 9, d = u & (DIN - 1);
        sh_in[u] = pooled[((b * N_ + sh_id[f]) << 9) + d];
    }

    // sinusoidal embedding: half=128, freq_j = exp(-ln(10000)*j/127)
    int   j    = c & 127;
    float fq   = expf(-9.210340371976184f * (float)j * (1.0f / 127.0f));
    bool  iscos = (c >= 128);
#pragma unroll
    for (int f = 0; f < FR; f++) {
        float r = rel_pos[b * T_ + t0 + f];
        float a = r * fq;
        sh_pos[f * C_ + c] = iscos ? cosf(a) : sinf(a);
    }
    __syncthreads();

    float acc[FR];
    float bias = b_in[c] + b_pos[c];
#pragma unroll
    for (int f = 0; f < FR; f++) acc[f] = bias;

    for (int d = 0; d < DIN; d++) {
        float w = W_in[d * C_ + c];
#pragma unroll
        for (int f = 0; f < FR; f++) acc[f] = fmaf(sh_in[f * DIN + d], w, acc[f]);
    }
    for (int q = 0; q < C_; q++) {
        float w = W_pos[q * C_ + c];
#pragma unroll
        for (int f = 0; f < FR; f++) acc[f] = fmaf(sh_pos[f * C_ + q], w, acc[f]);
    }
#pragma unroll
    for (int f = 0; f < FR; f++)
        g_x[((b * T_ + t0 + f) << 8) + c] = acc[f];
}

// ---------------------------------------------------------------------------
// Kernel 3: LN + exact GELU  (x -> h). One warp per frame, 8 frames/block.
// ---------------------------------------------------------------------------
__device__ __forceinline__ float warp_sum(float v) {
#pragma unroll
    for (int off = 16; off; off >>= 1)
        v += __shfl_xor_sync(0xffffffffu, v, off);
    return v;
}

__global__ __launch_bounds__(256) void lngelu_kernel(
    const float* __restrict__ ln_g, const float* __restrict__ ln_b, int l)
{
    int warp = threadIdx.x >> 5, lane = threadIdx.x & 31;
    int frame = blockIdx.x * 8 + warp;
    const float* xr = g_x + ((size_t)frame << 8);

    float v[8];
#pragma unroll
    for (int i = 0; i < 8; i++) v[i] = xr[lane + 32 * i];

    float s = 0.f;
#pragma unroll
    for (int i = 0; i < 8; i++) s += v[i];
    float mean = warp_sum(s) * (1.0f / C_);

    float s2 = 0.f;
#pragma unroll
    for (int i = 0; i < 8; i++) { float d = v[i] - mean; s2 += d * d; }
    float rstd = rsqrtf(warp_sum(s2) * (1.0f / C_) + EPS_);

    float* hr = g_h + ((size_t)frame << 8);
#pragma unroll
    for (int i = 0; i < 8; i++) {
        int ch = lane + 32 * i;
        float y = (v[i] - mean) * rstd * ln_g[l * C_ + ch] + ln_b[l * C_ + ch];
        // exact GELU: 0.5*y*(1+erf(y/sqrt(2)))
        hr[ch] = 0.5f * y * (1.0f + erff(y * 0.70710678118654752f));
    }
}

// ---------------------------------------------------------------------------
// Kernel 4: causal conv (K=31, C=256->256) + residual, in-place on g_x.
//   y[b,t,o] = x[b,t,o] + cb[o] + sum_{i,k} h[b, t+k-30, i] * w[o,i,k]
// Block: 16-frame tile, 512 threads = 2 frame-groups x 256 out-channels.
// Per-thread register window of 38 h-values reused across all 31 taps.
// ---------------------------------------------------------------------------
#define CTT 16   // frames per block tile
#define CFT 8    // frames per thread
#define CWIN (CFT + K_ - 1)   // 38

__global__ __launch_bounds__(512) void conv_kernel(
    const float* __restrict__ conv_w, const float* __restrict__ conv_b, int l)
{
    __shared__ float sh[(CTT + K_ - 1) * C_];   // 46*256*4 = 47104 B

    int tid = threadIdx.x;
    int o   = tid & (C_ - 1);
    int grp = tid >> 8;                 // 0 or 1
    int tilesPerBatch = T_ / CTT;       // 512
    int b  = blockIdx.x / tilesPerBatch;
    int t0 = (blockIdx.x % tilesPerBatch) * CTT;

    for (int u = tid; u < (CTT + K_ - 1) * C_; u += 512) {
        int jrow = u >> 8, ch = u & (C_ - 1);
        int t = t0 - (K_ - 1) + jrow;
        sh[u] = (t >= 0) ? g_h[((size_t)(b * T_ + t) << 8) + ch] : 0.0f;
    }
    __syncthreads();

    float acc[CFT];
#pragma unroll
    for (int f = 0; f < CFT; f++) acc[f] = 0.0f;

    const float* Wo = conv_w + (size_t)((l * C_ + o) * C_) * K_;
    int base = grp * CFT;               // 0 or 8

    for (int i = 0; i < C_; i++) {
        float v[CWIN];
#pragma unroll
        for (int jj = 0; jj < CWIN; jj++)
            v[jj] = sh[(base + jj) * C_ + i];   // broadcast LDS (same addr per warp)
        const float* wi = Wo + i * K_;
#pragma unroll
        for (int k = 0; k < K_; k++) {
            float w = __ldg(wi + k);
#pragma unroll
            for (int f = 0; f < CFT; f++)
                acc[f] = fmaf(v[f + k], w, acc[f]);
        }
    }

    float cb = conv_b[l * C_ + o];
#pragma unroll
    for (int f = 0; f < CFT; f++) {
        int t = t0 + base + f;
        size_t id = ((size_t)(b * T_ + t) << 8) + o;
        g_x[id] = g_x[id] + acc[f] + cb;
    }
}

// ---------------------------------------------------------------------------
// Kernel 5: final layer norm -> d_out
// ---------------------------------------------------------------------------
__global__ __launch_bounds__(256) void final_ln_kernel(
    const float* __restrict__ out_g, const float* __restrict__ out_b,
    float* __restrict__ out)
{
    int warp = threadIdx.x >> 5, lane = threadIdx.x & 31;
    int frame = blockIdx.x * 8 + warp;
    const float* xr = g_x + ((size_t)frame << 8);

    float v[8];
#pragma unroll
    for (int i = 0; i < 8; i++) v[i] = xr[lane + 32 * i];

    float s = 0.f;
#pragma unroll
    for (int i = 0; i < 8; i++) s += v[i];
    float mean = warp_sum(s) * (1.0f / C_);

    float s2 = 0.f;
#pragma unroll
    for (int i = 0; i < 8; i++) { float d = v[i] - mean; s2 += d * d; }
    float rstd = rsqrtf(warp_sum(s2) * (1.0f / C_) + EPS_);

    float* orow = out + ((size_t)frame << 8);
#pragma unroll
    for (int i = 0; i < 8; i++) {
        int ch = lane + 32 * i;
        orow[ch] = (v[i] - mean) * rstd * out_g[ch] + out_b[ch];
    }
}

// ---------------------------------------------------------------------------
extern "C" void kernel_launch(void* const* d_in, const int* in_sizes, int n_in,
                              void* d_out, int out_size)
{
    const float* pooled    = (const float*)d_in[0];
    const int*   durations = (const int*)  d_in[1];
    const float* rel_pos   = (const float*)d_in[2];
    const float* W_in      = (const float*)d_in[3];
    const float* b_in      = (const float*)d_in[4];
    const float* W_pos     = (const float*)d_in[5];
    const float* b_pos     = (const float*)d_in[6];
    const float* ln_g      = (const float*)d_in[7];
    const float* ln_b      = (const float*)d_in[8];
    const float* conv_w    = (const float*)d_in[9];
    const float* conv_b    = (const float*)d_in[10];
    const float* out_g     = (const float*)d_in[11];
    const float* out_b     = (const float*)d_in[12];
    float* out = (float*)d_out;

    idx_kernel<<<B_, 256>>>(durations);
    inproj_kernel<<<dim3(T_ / FR, B_), 256>>>(pooled, rel_pos, W_in, b_in, W_pos, b_pos);
    for (int l = 0; l < L_; l++) {
        lngelu_kernel<<<B_ * T_ / 8, 256>>>(ln_g, ln_b, l);
        conv_kernel<<<B_ * T_ / CTT, 512>>>(conv_w, conv_b, l);
    }
    final_ln_kernel<<<B_ * T_ / 8, 256>>>(out_g, out_b, out);
}

// round 2
// speedup vs baseline: 10.8435x; 10.8435x over previous
#include <cuda_runtime.h>
#include <math.h>

#define B_ 8
#define N_ 1024
#define DIN 512
#define C_ 256
#define T_ 8192
#define K_ 31
#define L_ 3
#define EPS_ 1e-5f

typedef unsigned long long ull;

// scratch (allocation-free rule: device globals)
__device__ float g_x[B_ * T_ * C_];          // 64 MB
__device__ float g_h[B_ * T_ * C_];          // 64 MB
__device__ float g_p[B_ * N_ * C_];          // 8 MB  phoneme projections
__device__ ull   g_w2[L_ * (C_/2) * K_ * C_]; // 24 MB transposed packed weights
__device__ int   g_idx[B_ * T_];

// ---------------------------------------------------------------------------
// f32x2 packed helpers (B300: fma.rn.f32x2, 2 FMA lanes per instr)
// ---------------------------------------------------------------------------
__device__ __forceinline__ ull pack2(float x, float y) {
    ull r; asm("mov.b64 %0, {%1, %2};" : "=l"(r) : "f"(x), "f"(y)); return r;
}
__device__ __forceinline__ void unpack2(float& x, float& y, ull v) {
    asm("mov.b64 {%0, %1}, %2;" : "=f"(x), "=f"(y) : "l"(v));
}
#define FMA2(d, a, b, c) asm("fma.rn.f32x2 %0, %1, %2, %3;" : "=l"(d) : "l"(a), "l"(b), "l"(c))

// ---------------------------------------------------------------------------
// Kernel 1: frame -> phoneme index (parallel scan + binary search)
// ---------------------------------------------------------------------------
__global__ __launch_bounds__(256) void idx_kernel(const int* __restrict__ durations) {
    __shared__ int cum[N_];
    __shared__ int wsum[8];
    int b = blockIdx.x, tid = threadIdx.x;
    int lane = tid & 31, warp = tid >> 5;

    int d[4], inc[4];
    int s = 0;
#pragma unroll
    for (int i = 0; i < 4; i++) {
        d[i] = durations[b * N_ + tid * 4 + i];
        s += d[i];
        inc[i] = s;
    }
    int x = s;
#pragma unroll
    for (int off = 1; off < 32; off <<= 1) {
        int y = __shfl_up_sync(0xffffffffu, x, off);
        if (lane >= off) x += y;
    }
    if (lane == 31) wsum[warp] = x;
    __syncthreads();
    if (tid == 0) {
        int acc = 0;
#pragma unroll
        for (int w = 0; w < 8; w++) { int v = wsum[w]; wsum[w] = acc; acc += v; }
    }
    __syncthreads();
    int excl = wsum[warp] + (x - s);
#pragma unroll
    for (int i = 0; i < 4; i++) cum[tid * 4 + i] = excl + inc[i];
    __syncthreads();

    for (int t = tid; t < T_; t += 256) {
        int lo = 0, hi = N_ - 1;
        while (lo < hi) {
            int mid = (lo + hi) >> 1;
            if (cum[mid] > t) hi = mid; else lo = mid + 1;
        }
        g_idx[b * T_ + t] = lo;
    }
}

// ---------------------------------------------------------------------------
// Kernel 2: transpose conv weights  conv_w[l][o][i][k] -> g_w2[l][i/2][k][o]{2}
// ---------------------------------------------------------------------------
__global__ __launch_bounds__(256) void transpose_w_kernel(const float* __restrict__ conv_w) {
    int blk = blockIdx.x;          // l * 128*31 + i2 * 31 + k
    int k  = blk % K_;
    int i2 = (blk / K_) % (C_/2);
    int l  = blk / (K_ * (C_/2));
    int o  = threadIdx.x;
    float a = conv_w[((size_t)(l * C_ + o) * C_ + 2 * i2    ) * K_ + k];
    float c = conv_w[((size_t)(l * C_ + o) * C_ + 2 * i2 + 1) * K_ + k];
    g_w2[((size_t)(l * (C_/2) + i2) * K_ + k) * C_ + o] = pack2(a, c);
}

// ---------------------------------------------------------------------------
// Kernel 3: phoneme projection GEMM:  g_p[row, c] = pooled[row,:] @ W_in + b_in
//   M = B*N = 8192, K = 512, N = 256.  Block tile 64x256, 512 thr, thread 8x4.
// ---------------------------------------------------------------------------
__global__ __launch_bounds__(512) void phoneme_proj_kernel(
    const float* __restrict__ pooled, const float* __restrict__ W_in,
    const float* __restrict__ b_in)
{
    __shared__ float sA[32][68];
    __shared__ float sW[32][256];

    int tid = threadIdx.x;
    int r = tid >> 6, cg = tid & 63;
    int row0 = blockIdx.x * 64;
    int fA = tid >> 3, kqA = tid & 7;

    float4 acc[8];
#pragma unroll
    for (int j = 0; j < 8; j++) acc[j] = make_float4(0.f, 0.f, 0.f, 0.f);

    for (int kt = 0; kt < DIN / 32; kt++) {
        __syncthreads();
        float4 av = *(const float4*)(pooled + (size_t)(row0 + fA) * DIN + kt * 32 + kqA * 4);
        sA[kqA * 4 + 0][fA] = av.x; sA[kqA * 4 + 1][fA] = av.y;
        sA[kqA * 4 + 2][fA] = av.z; sA[kqA * 4 + 3][fA] = av.w;
#pragma unroll
        for (int q = 0; q < 4; q++) {
            int e = tid + q * 512;
            int kk = e >> 6, c4 = e & 63;
            *(float4*)&sW[kk][c4 * 4] =
                *(const float4*)(W_in + (size_t)(kt * 32 + kk) * C_ + c4 * 4);
        }
        __syncthreads();
#pragma unroll
        for (int kk = 0; kk < 32; kk++) {
            float4 a0 = *(const float4*)&sA[kk][r * 8];
            float4 a1 = *(const float4*)&sA[kk][r * 8 + 4];
            float4 w  = *(const float4*)&sW[kk][cg * 4];
            acc[0].x = fmaf(a0.x, w.x, acc[0].x); acc[0].y = fmaf(a0.x, w.y, acc[0].y);
            acc[0].z = fmaf(a0.x, w.z, acc[0].z); acc[0].w = fmaf(a0.x, w.w, acc[0].w);
            acc[1].x = fmaf(a0.y, w.x, acc[1].x); acc[1].y = fmaf(a0.y, w.y, acc[1].y);
            acc[1].z = fmaf(a0.y, w.z, acc[1].z); acc[1].w = fmaf(a0.y, w.w, acc[1].w);
            acc[2].x = fmaf(a0.z, w.x, acc[2].x); acc[2].y = fmaf(a0.z, w.y, acc[2].y);
            acc[2].z = fmaf(a0.z, w.z, acc[2].z); acc[2].w = fmaf(a0.z, w.w, acc[2].w);
            acc[3].x = fmaf(a0.w, w.x, acc[3].x); acc[3].y = fmaf(a0.w, w.y, acc[3].y);
            acc[3].z = fmaf(a0.w, w.z, acc[3].z); acc[3].w = fmaf(a0.w, w.w, acc[3].w);
            acc[4].x = fmaf(a1.x, w.x, acc[4].x); acc[4].y = fmaf(a1.x, w.y, acc[4].y);
            acc[4].z = fmaf(a1.x, w.z, acc[4].z); acc[4].w = fmaf(a1.x, w.w, acc[4].w);
            acc[5].x = fmaf(a1.y, w.x, acc[5].x); acc[5].y = fmaf(a1.y, w.y, acc[5].y);
            acc[5].z = fmaf(a1.y, w.z, acc[5].z); acc[5].w = fmaf(a1.y, w.w, acc[5].w);
            acc[6].x = fmaf(a1.z, w.x, acc[6].x); acc[6].y = fmaf(a1.z, w.y, acc[6].y);
            acc[6].z = fmaf(a1.z, w.z, acc[6].z); acc[6].w = fmaf(a1.z, w.w, acc[6].w);
            acc[7].x = fmaf(a1.w, w.x, acc[7].x); acc[7].y = fmaf(a1.w, w.y, acc[7].y);
            acc[7].z = fmaf(a1.w, w.z, acc[7].z); acc[7].w = fmaf(a1.w, w.w, acc[7].w);
        }
    }
    float4 bi = *(const float4*)(b_in + cg * 4);
#pragma unroll
    for (int j = 0; j < 8; j++) {
        int row = row0 + r * 8 + j;
        float4 v = acc[j];
        v.x += bi.x; v.y += bi.y; v.z += bi.z; v.w += bi.w;
        *(float4*)(g_p + (size_t)row * C_ + cg * 4) = v;
    }
}

// ---------------------------------------------------------------------------
// Kernel 4: pos-emb projection GEMM + gather-add of phoneme projections.
//   x[b,t,c] = g_p[b, idx[t], c] + pos(rel[b,t]) @ W_pos[:,c] + b_pos[c]
//   M = B*T, K = 256, N = 256.  Block tile 64x256, 512 thr.
// ---------------------------------------------------------------------------
__global__ __launch_bounds__(512) void posproj_kernel(
    const float* __restrict__ rel_pos, const float* __restrict__ W_pos,
    const float* __restrict__ b_pos)
{
    __shared__ float sA[32][68];
    __shared__ float sW[32][256];
    __shared__ float s_rel[64];
    __shared__ float s_freq[128];
    __shared__ int   s_id[64];

    int tid = threadIdx.x;
    int r = tid >> 6, cg = tid & 63;
    int b = blockIdx.y;
    int t0 = blockIdx.x * 64;
    int fA = tid >> 3, kqA = tid & 7;

    if (tid < 64) {
        s_rel[tid] = rel_pos[b * T_ + t0 + tid];
        s_id[tid]  = g_idx[b * T_ + t0 + tid];
    } else if (tid < 192) {
        int j = tid - 64;
        s_freq[j] = expf(-9.210340371976184f * (float)j * (1.0f / 127.0f));
    }
    __syncthreads();

    float4 acc[8];
#pragma unroll
    for (int j = 0; j < 8; j++) acc[j] = make_float4(0.f, 0.f, 0.f, 0.f);

    for (int kt = 0; kt < C_ / 32; kt++) {
        __syncthreads();
        float rv = s_rel[fA];
#pragma unroll
        for (int j = 0; j < 4; j++) {
            int k = kt * 32 + kqA * 4 + j;
            float arg = rv * s_freq[k & 127];
            sA[kqA * 4 + j][fA] = (k < 128) ? sinf(arg) : cosf(arg);
        }
#pragma unroll
        for (int q = 0; q < 4; q++) {
            int e = tid + q * 512;
            int kk = e >> 6, c4 = e & 63;
            *(float4*)&sW[kk][c4 * 4] =
                *(const float4*)(W_pos + (size_t)(kt * 32 + kk) * C_ + c4 * 4);
        }
        __syncthreads();
#pragma unroll
        for (int kk = 0; kk < 32; kk++) {
            float4 a0 = *(const float4*)&sA[kk][r * 8];
            float4 a1 = *(const float4*)&sA[kk][r * 8 + 4];
            float4 w  = *(const float4*)&sW[kk][cg * 4];
            acc[0].x = fmaf(a0.x, w.x, acc[0].x); acc[0].y = fmaf(a0.x, w.y, acc[0].y);
            acc[0].z = fmaf(a0.x, w.z, acc[0].z); acc[0].w = fmaf(a0.x, w.w, acc[0].w);
            acc[1].x = fmaf(a0.y, w.x, acc[1].x); acc[1].y = fmaf(a0.y, w.y, acc[1].y);
            acc[1].z = fmaf(a0.y, w.z, acc[1].z); acc[1].w = fmaf(a0.y, w.w, acc[1].w);
            acc[2].x = fmaf(a0.z, w.x, acc[2].x); acc[2].y = fmaf(a0.z, w.y, acc[2].y);
            acc[2].z = fmaf(a0.z, w.z, acc[2].z); acc[2].w = fmaf(a0.z, w.w, acc[2].w);
            acc[3].x = fmaf(a0.w, w.x, acc[3].x); acc[3].y = fmaf(a0.w, w.y, acc[3].y);
            acc[3].z = fmaf(a0.w, w.z, acc[3].z); acc[3].w = fmaf(a0.w, w.w, acc[3].w);
            acc[4].x = fmaf(a1.x, w.x, acc[4].x); acc[4].y = fmaf(a1.x, w.y, acc[4].y);
            acc[4].z = fmaf(a1.x, w.z, acc[4].z); acc[4].w = fmaf(a1.x, w.w, acc[4].w);
            acc[5].x = fmaf(a1.y, w.x, acc[5].x); acc[5].y = fmaf(a1.y, w.y, acc[5].y);
            acc[5].z = fmaf(a1.y, w.z, acc[5].z); acc[5].w = fmaf(a1.y, w.w, acc[5].w);
            acc[6].x = fmaf(a1.z, w.x, acc[6].x); acc[6].y = fmaf(a1.z, w.y, acc[6].y);
            acc[6].z = fmaf(a1.z, w.z, acc[6].z); acc[6].w = fmaf(a1.z, w.w, acc[6].w);
            acc[7].x = fmaf(a1.w, w.x, acc[7].x); acc[7].y = fmaf(a1.w, w.y, acc[7].y);
            acc[7].z = fmaf(a1.w, w.z, acc[7].z); acc[7].w = fmaf(a1.w, w.w, acc[7].w);
        }
    }
    float4 bp = *(const float4*)(b_pos + cg * 4);
#pragma unroll
    for (int j = 0; j < 8; j++) {
        int f = r * 8 + j;
        int ph = s_id[f];
        float4 pv = *(const float4*)(g_p + ((size_t)(b * N_ + ph) << 8) + cg * 4);
        float4 v = acc[j];
        v.x += bp.x + pv.x; v.y += bp.y + pv.y;
        v.z += bp.z + pv.z; v.w += bp.w + pv.w;
        *(float4*)(g_x + ((size_t)(b * T_ + t0 + f) << 8) + cg * 4) = v;
    }
}

// ---------------------------------------------------------------------------
// Kernel 5: LN + exact GELU  (x -> h). One warp per frame.
// ---------------------------------------------------------------------------
__device__ __forceinline__ float warp_sum(float v) {
#pragma unroll
    for (int off = 16; off; off >>= 1)
        v += __shfl_xor_sync(0xffffffffu, v, off);
    return v;
}

__global__ __launch_bounds__(256) void lngelu_kernel(
    const float* __restrict__ ln_g, const float* __restrict__ ln_b, int l)
{
    int warp = threadIdx.x >> 5, lane = threadIdx.x & 31;
    int frame = blockIdx.x * 8 + warp;
    const float* xr = g_x + ((size_t)frame << 8);

    float v[8];
#pragma unroll
    for (int i = 0; i < 8; i++) v[i] = xr[lane + 32 * i];

    float s = 0.f;
#pragma unroll
    for (int i = 0; i < 8; i++) s += v[i];
    float mean = warp_sum(s) * (1.0f / C_);

    float s2 = 0.f;
#pragma unroll
    for (int i = 0; i < 8; i++) { float d = v[i] - mean; s2 += d * d; }
    float rstd = rsqrtf(warp_sum(s2) * (1.0f / C_) + EPS_);

    float* hr = g_h + ((size_t)frame << 8);
#pragma unroll
    for (int i = 0; i < 8; i++) {
        int ch = lane + 32 * i;
        float y = (v[i] - mean) * rstd * ln_g[l * C_ + ch] + ln_b[l * C_ + ch];
        hr[ch] = 0.5f * y * (1.0f + erff(y * 0.70710678118654752f));
    }
}

// ---------------------------------------------------------------------------
// Kernel 6: causal conv (K=31, 256->256) + residual, packed f32x2 over
// input-channel pairs, coalesced transposed weights.
// ---------------------------------------------------------------------------
#define CTT 16
#define CFT 8
#define CWIN (CFT + K_ - 1)   // 38

__global__ __launch_bounds__(512) void conv_kernel(
    const float* __restrict__ conv_b, int l)
{
    __shared__ float sh[(CTT + K_ - 1) * C_];   // 46*256*4 = 47104 B

    int tid = threadIdx.x;
    int o   = tid & (C_ - 1);
    int grp = tid >> 8;
    int tilesPerBatch = T_ / CTT;
    int b  = blockIdx.x / tilesPerBatch;
    int t0 = (blockIdx.x % tilesPerBatch) * CTT;

    for (int u = tid; u < (CTT + K_ - 1) * C_; u += 512) {
        int jrow = u >> 8, ch = u & (C_ - 1);
        int t = t0 - (K_ - 1) + jrow;
        sh[u] = (t >= 0) ? g_h[((size_t)(b * T_ + t) << 8) + ch] : 0.0f;
    }
    __syncthreads();

    ull acc2[CFT];
#pragma unroll
    for (int f = 0; f < CFT; f++) acc2[f] = 0ull;

    const ull* Wl = g_w2 + (size_t)l * (C_/2) * K_ * C_ + o;
    int base = grp * CFT;

    for (int i2 = 0; i2 < C_ / 2; i2++) {
        ull vv[CWIN];
#pragma unroll
        for (int jj = 0; jj < CWIN; jj++)
            vv[jj] = *(const ull*)&sh[(base + jj) * C_ + 2 * i2];   // broadcast LDS.64
        const ull* wp = Wl + (size_t)i2 * K_ * C_;
#pragma unroll
        for (int k = 0; k < K_; k++) {
            ull w2 = __ldg(wp + k * C_);
#pragma unroll
            for (int f = 0; f < CFT; f++)
                FMA2(acc2[f], vv[f + k], w2, acc2[f]);
        }
    }

    float cb = conv_b[l * C_ + o];
#pragma unroll
    for (int f = 0; f < CFT; f++) {
        float lo, hi;
        unpack2(lo, hi, acc2[f]);
        int t = t0 + base + f;
        size_t id = ((size_t)(b * T_ + t) << 8) + o;
        g_x[id] = g_x[id] + lo + hi + cb;
    }
}

// ---------------------------------------------------------------------------
// Kernel 7: final layer norm -> d_out
// ---------------------------------------------------------------------------
__global__ __launch_bounds__(256) void final_ln_kernel(
    const float* __restrict__ out_g, const float* __restrict__ out_b,
    float* __restrict__ out)
{
    int warp = threadIdx.x >> 5, lane = threadIdx.x & 31;
    int frame = blockIdx.x * 8 + warp;
    const float* xr = g_x + ((size_t)frame << 8);

    float v[8];
#pragma unroll
    for (int i = 0; i < 8; i++) v[i] = xr[lane + 32 * i];

    float s = 0.f;
#pragma unroll
    for (int i = 0; i < 8; i++) s += v[i];
    float mean = warp_sum(s) * (1.0f / C_);

    float s2 = 0.f;
#pragma unroll
    for (int i = 0; i < 8; i++) { float d = v[i] - mean; s2 += d * d; }
    float rstd = rsqrtf(warp_sum(s2) * (1.0f / C_) + EPS_);

    float* orow = out + ((size_t)frame << 8);
#pragma unroll
    for (int i = 0; i < 8; i++) {
        int ch = lane + 32 * i;
        orow[ch] = (v[i] - mean) * rstd * out_g[ch] + out_b[ch];
    }
}

// ---------------------------------------------------------------------------
extern "C" void kernel_launch(void* const* d_in, const int* in_sizes, int n_in,
                              void* d_out, int out_size)
{
    const float* pooled    = (const float*)d_in[0];
    const int*   durations = (const int*)  d_in[1];
    const float* rel_pos   = (const float*)d_in[2];
    const float* W_in      = (const float*)d_in[3];
    const float* b_in      = (const float*)d_in[4];
    const float* W_pos     = (const float*)d_in[5];
    const float* b_pos     = (const float*)d_in[6];
    const float* ln_g      = (const float*)d_in[7];
    const float* ln_b      = (const float*)d_in[8];
    const float* conv_w    = (const float*)d_in[9];
    const float* conv_b    = (const float*)d_in[10];
    const float* out_g     = (const float*)d_in[11];
    const float* out_b     = (const float*)d_in[12];
    float* out = (float*)d_out;

    idx_kernel<<<B_, 256>>>(durations);
    transpose_w_kernel<<<L_ * (C_/2) * K_, 256>>>(conv_w);
    phoneme_proj_kernel<<<B_ * N_ / 64, 512>>>(pooled, W_in, b_in);
    posproj_kernel<<<dim3(T_ / 64, B_), 512>>>(rel_pos, W_pos, b_pos);
    for (int l = 0; l < L_; l++) {
        lngelu_kernel<<<B_ * T_ / 8, 256>>>(ln_g, ln_b, l);
        conv_kernel<<<B_ * T_ / CTT, 512>>>(conv_b, l);
    }
    final_ln_kernel<<<B_ * T_ / 8, 256>>>(out_g, out_b, out);
}

// round 3
// speedup vs baseline: 11.4678x; 1.0576x over previous
#include <cuda_runtime.h>
#include <math.h>

#define B_ 8
#define N_ 1024
#define DIN 512
#define C_ 256
#define T_ 8192
#define K_ 31
#define L_ 3
#define EPS_ 1e-5f

typedef unsigned long long ull;

// scratch (allocation-free rule: device globals)
__device__ float g_x[B_ * T_ * C_];          // 64 MB
__device__ float g_h[B_ * T_ * C_];          // 64 MB
__device__ float g_p[B_ * N_ * C_];          // 8 MB  phoneme projections
__device__ ull   g_w2[L_ * (C_/2) * K_ * C_]; // 24 MB transposed packed weights
__device__ int   g_idx[B_ * T_];

// ---------------------------------------------------------------------------
// f32x2 packed helpers (B300: fma.rn.f32x2, 2 FMA lanes per instr)
// ---------------------------------------------------------------------------
__device__ __forceinline__ ull pack2(float x, float y) {
    ull r; asm("mov.b64 %0, {%1, %2};" : "=l"(r) : "f"(x), "f"(y)); return r;
}
__device__ __forceinline__ void unpack2(float& x, float& y, ull v) {
    asm("mov.b64 {%0, %1}, %2;" : "=f"(x), "=f"(y) : "l"(v));
}
#define FMA2(d, a, b, c) asm("fma.rn.f32x2 %0, %1, %2, %3;" : "=l"(d) : "l"(a), "l"(b), "l"(c))

// ---------------------------------------------------------------------------
// Kernel 1: frame -> phoneme index (parallel scan + binary search)
// ---------------------------------------------------------------------------
__global__ __launch_bounds__(256) void idx_kernel(const int* __restrict__ durations) {
    __shared__ int cum[N_];
    __shared__ int wsum[8];
    int b = blockIdx.x, tid = threadIdx.x;
    int lane = tid & 31, warp = tid >> 5;

    int d[4], inc[4];
    int s = 0;
#pragma unroll
    for (int i = 0; i < 4; i++) {
        d[i] = durations[b * N_ + tid * 4 + i];
        s += d[i];
        inc[i] = s;
    }
    int x = s;
#pragma unroll
    for (int off = 1; off < 32; off <<= 1) {
        int y = __shfl_up_sync(0xffffffffu, x, off);
        if (lane >= off) x += y;
    }
    if (lane == 31) wsum[warp] = x;
    __syncthreads();
    if (tid == 0) {
        int acc = 0;
#pragma unroll
        for (int w = 0; w < 8; w++) { int v = wsum[w]; wsum[w] = acc; acc += v; }
    }
    __syncthreads();
    int excl = wsum[warp] + (x - s);
#pragma unroll
    for (int i = 0; i < 4; i++) cum[tid * 4 + i] = excl + inc[i];
    __syncthreads();

    for (int t = tid; t < T_; t += 256) {
        int lo = 0, hi = N_ - 1;
        while (lo < hi) {
            int mid = (lo + hi) >> 1;
            if (cum[mid] > t) hi = mid; else lo = mid + 1;
        }
        g_idx[b * T_ + t] = lo;
    }
}

// ---------------------------------------------------------------------------
// Kernel 2: transpose conv weights  conv_w[l][o][i][k] -> g_w2[l][i/2][k][o]{2}
// ---------------------------------------------------------------------------
__global__ __launch_bounds__(256) void transpose_w_kernel(const float* __restrict__ conv_w) {
    int blk = blockIdx.x;          // l * 128*31 + i2 * 31 + k
    int k  = blk % K_;
    int i2 = (blk / K_) % (C_/2);
    int l  = blk / (K_ * (C_/2));
    int o  = threadIdx.x;
    float a = conv_w[((size_t)(l * C_ + o) * C_ + 2 * i2    ) * K_ + k];
    float c = conv_w[((size_t)(l * C_ + o) * C_ + 2 * i2 + 1) * K_ + k];
    g_w2[((size_t)(l * (C_/2) + i2) * K_ + k) * C_ + o] = pack2(a, c);
}

// ---------------------------------------------------------------------------
// Kernel 3: phoneme projection GEMM:  g_p[row, c] = pooled[row,:] @ W_in + b_in
//   M = B*N = 8192, K = 512, N = 256.  Block tile 64x256, 512 thr, thread 8x4.
// ---------------------------------------------------------------------------
__global__ __launch_bounds__(512) void phoneme_proj_kernel(
    const float* __restrict__ pooled, const float* __restrict__ W_in,
    const float* __restrict__ b_in)
{
    __shared__ float sA[32][68];
    __shared__ float sW[32][256];

    int tid = threadIdx.x;
    int r = tid >> 6, cg = tid & 63;
    int row0 = blockIdx.x * 64;
    int fA = tid >> 3, kqA = tid & 7;

    float4 acc[8];
#pragma unroll
    for (int j = 0; j < 8; j++) acc[j] = make_float4(0.f, 0.f, 0.f, 0.f);

    for (int kt = 0; kt < DIN / 32; kt++) {
        __syncthreads();
        float4 av = *(const float4*)(pooled + (size_t)(row0 + fA) * DIN + kt * 32 + kqA * 4);
        sA[kqA * 4 + 0][fA] = av.x; sA[kqA * 4 + 1][fA] = av.y;
        sA[kqA * 4 + 2][fA] = av.z; sA[kqA * 4 + 3][fA] = av.w;
#pragma unroll
        for (int q = 0; q < 4; q++) {
            int e = tid + q * 512;
            int kk = e >> 6, c4 = e & 63;
            *(float4*)&sW[kk][c4 * 4] =
                *(const float4*)(W_in + (size_t)(kt * 32 + kk) * C_ + c4 * 4);
        }
        __syncthreads();
#pragma unroll
        for (int kk = 0; kk < 32; kk++) {
            float4 a0 = *(const float4*)&sA[kk][r * 8];
            float4 a1 = *(const float4*)&sA[kk][r * 8 + 4];
            float4 w  = *(const float4*)&sW[kk][cg * 4];
            acc[0].x = fmaf(a0.x, w.x, acc[0].x); acc[0].y = fmaf(a0.x, w.y, acc[0].y);
            acc[0].z = fmaf(a0.x, w.z, acc[0].z); acc[0].w = fmaf(a0.x, w.w, acc[0].w);
            acc[1].x = fmaf(a0.y, w.x, acc[1].x); acc[1].y = fmaf(a0.y, w.y, acc[1].y);
            acc[1].z = fmaf(a0.y, w.z, acc[1].z); acc[1].w = fmaf(a0.y, w.w, acc[1].w);
            acc[2].x = fmaf(a0.z, w.x, acc[2].x); acc[2].y = fmaf(a0.z, w.y, acc[2].y);
            acc[2].z = fmaf(a0.z, w.z, acc[2].z); acc[2].w = fmaf(a0.z, w.w, acc[2].w);
            acc[3].x = fmaf(a0.w, w.x, acc[3].x); acc[3].y = fmaf(a0.w, w.y, acc[3].y);
            acc[3].z = fmaf(a0.w, w.z, acc[3].z); acc[3].w = fmaf(a0.w, w.w, acc[3].w);
            acc[4].x = fmaf(a1.x, w.x, acc[4].x); acc[4].y = fmaf(a1.x, w.y, acc[4].y);
            acc[4].z = fmaf(a1.x, w.z, acc[4].z); acc[4].w = fmaf(a1.x, w.w, acc[4].w);
            acc[5].x = fmaf(a1.y, w.x, acc[5].x); acc[5].y = fmaf(a1.y, w.y, acc[5].y);
            acc[5].z = fmaf(a1.y, w.z, acc[5].z); acc[5].w = fmaf(a1.y, w.w, acc[5].w);
            acc[6].x = fmaf(a1.z, w.x, acc[6].x); acc[6].y = fmaf(a1.z, w.y, acc[6].y);
            acc[6].z = fmaf(a1.z, w.z, acc[6].z); acc[6].w = fmaf(a1.z, w.w, acc[6].w);
            acc[7].x = fmaf(a1.w, w.x, acc[7].x); acc[7].y = fmaf(a1.w, w.y, acc[7].y);
            acc[7].z = fmaf(a1.w, w.z, acc[7].z); acc[7].w = fmaf(a1.w, w.w, acc[7].w);
        }
    }
    float4 bi = *(const float4*)(b_in + cg * 4);
#pragma unroll
    for (int j = 0; j < 8; j++) {
        int row = row0 + r * 8 + j;
        float4 v = acc[j];
        v.x += bi.x; v.y += bi.y; v.z += bi.z; v.w += bi.w;
        *(float4*)(g_p + (size_t)row * C_ + cg * 4) = v;
    }
}

// ---------------------------------------------------------------------------
// Kernel 4: pos-emb projection GEMM + gather-add of phoneme projections.
//   x[b,t,c] = g_p[b, idx[t], c] + pos(rel[b,t]) @ W_pos[:,c] + b_pos[c]
//   M = B*T, K = 256, N = 256.  Block tile 64x256, 512 thr.
// ---------------------------------------------------------------------------
__global__ __launch_bounds__(512) void posproj_kernel(
    const float* __restrict__ rel_pos, const float* __restrict__ W_pos,
    const float* __restrict__ b_pos)
{
    __shared__ float sA[32][68];
    __shared__ float sW[32][256];
    __shared__ float s_rel[64];
    __shared__ float s_freq[128];
    __shared__ int   s_id[64];

    int tid = threadIdx.x;
    int r = tid >> 6, cg = tid & 63;
    int b = blockIdx.y;
    int t0 = blockIdx.x * 64;
    int fA = tid >> 3, kqA = tid & 7;

    if (tid < 64) {
        s_rel[tid] = rel_pos[b * T_ + t0 + tid];
        s_id[tid]  = g_idx[b * T_ + t0 + tid];
    } else if (tid < 192) {
        int j = tid - 64;
        s_freq[j] = expf(-9.210340371976184f * (float)j * (1.0f / 127.0f));
    }
    __syncthreads();

    float4 acc[8];
#pragma unroll
    for (int j = 0; j < 8; j++) acc[j] = make_float4(0.f, 0.f, 0.f, 0.f);

    for (int kt = 0; kt < C_ / 32; kt++) {
        __syncthreads();
        float rv = s_rel[fA];
#pragma unroll
        for (int j = 0; j < 4; j++) {
            int k = kt * 32 + kqA * 4 + j;
            float arg = rv * s_freq[k & 127];
            sA[kqA * 4 + j][fA] = (k < 128) ? sinf(arg) : cosf(arg);
        }
#pragma unroll
        for (int q = 0; q < 4; q++) {
            int e = tid + q * 512;
            int kk = e >> 6, c4 = e & 63;
            *(float4*)&sW[kk][c4 * 4] =
                *(const float4*)(W_pos + (size_t)(kt * 32 + kk) * C_ + c4 * 4);
        }
        __syncthreads();
#pragma unroll
        for (int kk = 0; kk < 32; kk++) {
            float4 a0 = *(const float4*)&sA[kk][r * 8];
            float4 a1 = *(const float4*)&sA[kk][r * 8 + 4];
            float4 w  = *(const float4*)&sW[kk][cg * 4];
            acc[0].x = fmaf(a0.x, w.x, acc[0].x); acc[0].y = fmaf(a0.x, w.y, acc[0].y);
            acc[0].z = fmaf(a0.x, w.z, acc[0].z); acc[0].w = fmaf(a0.x, w.w, acc[0].w);
            acc[1].x = fmaf(a0.y, w.x, acc[1].x); acc[1].y = fmaf(a0.y, w.y, acc[1].y);
            acc[1].z = fmaf(a0.y, w.z, acc[1].z); acc[1].w = fmaf(a0.y, w.w, acc[1].w);
            acc[2].x = fmaf(a0.z, w.x, acc[2].x); acc[2].y = fmaf(a0.z, w.y, acc[2].y);
            acc[2].z = fmaf(a0.z, w.z, acc[2].z); acc[2].w = fmaf(a0.z, w.w, acc[2].w);
            acc[3].x = fmaf(a0.w, w.x, acc[3].x); acc[3].y = fmaf(a0.w, w.y, acc[3].y);
            acc[3].z = fmaf(a0.w, w.z, acc[3].z); acc[3].w = fmaf(a0.w, w.w, acc[3].w);
            acc[4].x = fmaf(a1.x, w.x, acc[4].x); acc[4].y = fmaf(a1.x, w.y, acc[4].y);
            acc[4].z = fmaf(a1.x, w.z, acc[4].z); acc[4].w = fmaf(a1.x, w.w, acc[4].w);
            acc[5].x = fmaf(a1.y, w.x, acc[5].x); acc[5].y = fmaf(a1.y, w.y, acc[5].y);
            acc[5].z = fmaf(a1.y, w.z, acc[5].z); acc[5].w = fmaf(a1.y, w.w, acc[5].w);
            acc[6].x = fmaf(a1.z, w.x, acc[6].x); acc[6].y = fmaf(a1.z, w.y, acc[6].y);
            acc[6].z = fmaf(a1.z, w.z, acc[6].z); acc[6].w = fmaf(a1.z, w.w, acc[6].w);
            acc[7].x = fmaf(a1.w, w.x, acc[7].x); acc[7].y = fmaf(a1.w, w.y, acc[7].y);
            acc[7].z = fmaf(a1.w, w.z, acc[7].z); acc[7].w = fmaf(a1.w, w.w, acc[7].w);
        }
    }
    float4 bp = *(const float4*)(b_pos + cg * 4);
#pragma unroll
    for (int j = 0; j < 8; j++) {
        int f = r * 8 + j;
        int ph = s_id[f];
        float4 pv = *(const float4*)(g_p + ((size_t)(b * N_ + ph) << 8) + cg * 4);
        float4 v = acc[j];
        v.x += bp.x + pv.x; v.y += bp.y + pv.y;
        v.z += bp.z + pv.z; v.w += bp.w + pv.w;
        *(float4*)(g_x + ((size_t)(b * T_ + t0 + f) << 8) + cg * 4) = v;
    }
}

// ---------------------------------------------------------------------------
// Kernel 5: LN + exact GELU  (x -> h). One warp per frame.
// ---------------------------------------------------------------------------
__device__ __forceinline__ float warp_sum(float v) {
#pragma unroll
    for (int off = 16; off; off >>= 1)
        v += __shfl_xor_sync(0xffffffffu, v, off);
    return v;
}

__global__ __launch_bounds__(256) void lngelu_kernel(
    const float* __restrict__ ln_g, const float* __restrict__ ln_b, int l)
{
    int warp = threadIdx.x >> 5, lane = threadIdx.x & 31;
    int frame = blockIdx.x * 8 + warp;
    const float* xr = g_x + ((size_t)frame << 8);

    float v[8];
#pragma unroll
    for (int i = 0; i < 8; i++) v[i] = xr[lane + 32 * i];

    float s = 0.f;
#pragma unroll
    for (int i = 0; i < 8; i++) s += v[i];
    float mean = warp_sum(s) * (1.0f / C_);

    float s2 = 0.f;
#pragma unroll
    for (int i = 0; i < 8; i++) { float d = v[i] - mean; s2 += d * d; }
    float rstd = rsqrtf(warp_sum(s2) * (1.0f / C_) + EPS_);

    float* hr = g_h + ((size_t)frame << 8);
#pragma unroll
    for (int i = 0; i < 8; i++) {
        int ch = lane + 32 * i;
        float y = (v[i] - mean) * rstd * ln_g[l * C_ + ch] + ln_b[l * C_ + ch];
        hr[ch] = 0.5f * y * (1.0f + erff(y * 0.70710678118654752f));
    }
}

// ---------------------------------------------------------------------------
// Kernel 6: causal conv (K=31, 256->256) + residual, packed f32x2 over
// input-channel pairs, coalesced transposed weights.
// ---------------------------------------------------------------------------
#define CTT 16
#define CFT 8
#define CWIN (CFT + K_ - 1)   // 38

__global__ __launch_bounds__(512) void conv_kernel(
    const float* __restrict__ conv_b, int l)
{
    __shared__ float sh[(CTT + K_ - 1) * C_];   // 46*256*4 = 47104 B

    int tid = threadIdx.x;
    int o   = tid & (C_ - 1);
    int grp = tid >> 8;
    int tilesPerBatch = T_ / CTT;
    int b  = blockIdx.x / tilesPerBatch;
    int t0 = (blockIdx.x % tilesPerBatch) * CTT;

    for (int u = tid; u < (CTT + K_ - 1) * C_; u += 512) {
        int jrow = u >> 8, ch = u & (C_ - 1);
        int t = t0 - (K_ - 1) + jrow;
        sh[u] = (t >= 0) ? g_h[((size_t)(b * T_ + t) << 8) + ch] : 0.0f;
    }
    __syncthreads();

    ull acc2[CFT];
#pragma unroll
    for (int f = 0; f < CFT; f++) acc2[f] = 0ull;

    const ull* Wl = g_w2 + (size_t)l * (C_/2) * K_ * C_ + o;
    int base = grp * CFT;

    for (int i2 = 0; i2 < C_ / 2; i2++) {
        ull vv[CWIN];
#pragma unroll
        for (int jj = 0; jj < CWIN; jj++)
            vv[jj] = *(const ull*)&sh[(base + jj) * C_ + 2 * i2];   // broadcast LDS.64
        const ull* wp = Wl + (size_t)i2 * K_ * C_;
#pragma unroll
        for (int k = 0; k < K_; k++) {
            ull w2 = __ldg(wp + k * C_);
#pragma unroll
            for (int f = 0; f < CFT; f++)
                FMA2(acc2[f], vv[f + k], w2, acc2[f]);
        }
    }

    float cb = conv_b[l * C_ + o];
#pragma unroll
    for (int f = 0; f < CFT; f++) {
        float lo, hi;
        unpack2(lo, hi, acc2[f]);
        int t = t0 + base + f;
        size_t id = ((size_t)(b * T_ + t) << 8) + o;
        g_x[id] = g_x[id] + lo + hi + cb;
    }
}

// ---------------------------------------------------------------------------
// Kernel 7: final layer norm -> d_out
// ---------------------------------------------------------------------------
__global__ __launch_bounds__(256) void final_ln_kernel(
    const float* __restrict__ out_g, const float* __restrict__ out_b,
    float* __restrict__ out)
{
    int warp = threadIdx.x >> 5, lane = threadIdx.x & 31;
    int frame = blockIdx.x * 8 + warp;
    const float* xr = g_x + ((size_t)frame << 8);

    float v[8];
#pragma unroll
    for (int i = 0; i < 8; i++) v[i] = xr[lane + 32 * i];

    float s = 0.f;
#pragma unroll
    for (int i = 0; i < 8; i++) s += v[i];
    float mean = warp_sum(s) * (1.0f / C_);

    float s2 = 0.f;
#pragma unroll
    for (int i = 0; i < 8; i++) { float d = v[i] - mean; s2 += d * d; }
    float rstd = rsqrtf(warp_sum(s2) * (1.0f / C_) + EPS_);

    float* orow = out + ((size_t)frame << 8);
#pragma unroll
    for (int i = 0; i < 8; i++) {
        int ch = lane + 32 * i;
        orow[ch] = (v[i] - mean) * rstd * out_g[ch] + out_b[ch];
    }
}

// ---------------------------------------------------------------------------
extern "C" void kernel_launch(void* const* d_in, const int* in_sizes, int n_in,
                              void* d_out, int out_size)
{
    const float* pooled    = (const float*)d_in[0];
    const int*   durations = (const int*)  d_in[1];
    const float* rel_pos   = (const float*)d_in[2];
    const float* W_in      = (const float*)d_in[3];
    const float* b_in      = (const float*)d_in[4];
    const float* W_pos     = (const float*)d_in[5];
    const float* b_pos     = (const float*)d_in[6];
    const float* ln_g      = (const float*)d_in[7];
    const float* ln_b      = (const float*)d_in[8];
    const float* conv_w    = (const float*)d_in[9];
    const float* conv_b    = (const float*)d_in[10];
    const float* out_g     = (const float*)d_in[11];
    const float* out_b     = (const float*)d_in[12];
    float* out = (float*)d_out;

    idx_kernel<<<B_, 256>>>(durations);
    transpose_w_kernel<<<L_ * (C_/2) * K_, 256>>>(conv_w);
    phoneme_proj_kernel<<<B_ * N_ / 64, 512>>>(pooled, W_in, b_in);
    posproj_kernel<<<dim3(T_ / 64, B_), 512>>>(rel_pos, W_pos, b_pos);
    for (int l = 0; l < L_; l++) {
        lngelu_kernel<<<B_ * T_ / 8, 256>>>(ln_g, ln_b, l);
        conv_kernel<<<B_ * T_ / CTT, 512>>>(conv_b, l);
    }
    final_ln_kernel<<<B_ * T_ / 8, 256>>>(out_g, out_b, out);
}

// round 14
// speedup vs baseline: 22.6868x; 1.9783x over previous
#include <cuda_runtime.h>
#include <cuda_bf16.h>
#include <cstdint>
#include <stdint.h>
#include <math.h>

#define B_ 8
#define N_ 1024
#define DIN 512
#define C_ 256
#define T_ 8192
#define K_ 31
#define L_ 3
#define EPS_ 1e-5f
#define NZ (L_ * K_)

// device scratch (allocation-free rule)
__device__ __align__(1024) float g_x[B_ * T_ * C_];
__device__ __align__(1024) float g_p[B_ * N_ * C_];
__device__ __align__(1024) __nv_bfloat16 g_hAh[B_ * T_ * C_];
__device__ __align__(1024) __nv_bfloat16 g_hAl[B_ * T_ * C_];
__device__ __align__(1024) __nv_bfloat16 g_hBh[B_ * T_ * C_];
__device__ __align__(1024) __nv_bfloat16 g_hBl[B_ * T_ * C_];
__device__ __align__(1024) __nv_bfloat16 g_wh[NZ * C_ * C_];
__device__ __align__(1024) __nv_bfloat16 g_wl[NZ * C_ * C_];
__device__ int g_idx[B_ * T_];

// ---------------- PTX helpers ----------------
__device__ __forceinline__ uint32_t smem_u32(const void* p) {
    uint32_t a;
    asm("{ .reg .u64 t; cvta.to.shared.u64 t, %1; cvt.u32.u64 %0, t; }" : "=r"(a) : "l"(p));
    return a;
}
__device__ __forceinline__ void cpa16(uint32_t dst, const void* src, int sz) {
    asm volatile("cp.async.cg.shared.global [%0], [%1], 16, %2;"
                 :: "r"(dst), "l"(src), "r"(sz) : "memory");
}
#define CP_COMMIT() asm volatile("cp.async.commit_group;" ::: "memory")
#define CP_WAIT1()  asm volatile("cp.async.wait_group 1;" ::: "memory")

__device__ __forceinline__ void ldsm4(uint32_t* r, uint32_t a) {
    asm volatile("ldmatrix.sync.aligned.m8n8.x4.shared.b16 {%0,%1,%2,%3}, [%4];"
        : "=r"(r[0]), "=r"(r[1]), "=r"(r[2]), "=r"(r[3]) : "r"(a));
}
__device__ __forceinline__ void mma16816(float* c, const uint32_t* a, const uint32_t* b) {
    asm volatile("mma.sync.aligned.m16n8k16.row.col.f32.bf16.bf16.f32 "
        "{%0,%1,%2,%3}, {%4,%5,%6,%7}, {%8,%9}, {%0,%1,%2,%3};"
        : "+f"(c[0]), "+f"(c[1]), "+f"(c[2]), "+f"(c[3])
        : "r"(a[0]), "r"(a[1]), "r"(a[2]), "r"(a[3]), "r"(b[0]), "r"(b[1]));
}

// ---------------- idx kernel ----------------
__global__ __launch_bounds__(256) void idx_kernel(const int* __restrict__ durations) {
    __shared__ int cum[N_];
    __shared__ int wsum[8];
    int b = blockIdx.x, tid = threadIdx.x;
    int lane = tid & 31, warp = tid >> 5;
    int d[4], inc[4];
    int s = 0;
#pragma unroll
    for (int i = 0; i < 4; i++) { d[i] = durations[b * N_ + tid * 4 + i]; s += d[i]; inc[i] = s; }
    int x = s;
#pragma unroll
    for (int off = 1; off < 32; off <<= 1) {
        int y = __shfl_up_sync(0xffffffffu, x, off);
        if (lane >= off) x += y;
    }
    if (lane == 31) wsum[warp] = x;
    __syncthreads();
    if (tid == 0) {
        int acc = 0;
#pragma unroll
        for (int w = 0; w < 8; w++) { int v = wsum[w]; wsum[w] = acc; acc += v; }
    }
    __syncthreads();
    int excl = wsum[warp] + (x - s);
#pragma unroll
    for (int i = 0; i < 4; i++) cum[tid * 4 + i] = excl + inc[i];
    __syncthreads();
    for (int t = tid; t < T_; t += 256) {
        int lo = 0, hi = N_ - 1;
        while (lo < hi) { int m = (lo + hi) >> 1; if (cum[m] > t) hi = m; else lo = m + 1; }
        g_idx[b * T_ + t] = lo;
    }
}

// ---------------- weight split: conv_w[l][o][i][k] -> [z][o][i] hi/lo -------
__global__ __launch_bounds__(256) void wsplit_kernel(const float* __restrict__ cw) {
    int blk = blockIdx.x;                 // z*256 + o
    int o = blk & 255, z = blk >> 8;
    int l = z / K_, k = z - l * K_;
    int i = threadIdx.x;
    float w = cw[((size_t)((l * C_ + o) * C_ + i)) * K_ + k];
    __nv_bfloat16 h = __float2bfloat16_rn(w);
    float lo = w - __bfloat162float(h);
    size_t di = ((size_t)z * C_ + o) * C_ + i;
    g_wh[di] = h;
    g_wl[di] = __float2bfloat16_rn(lo);
}

// ---------------- phoneme projection GEMM ----------------
__global__ __launch_bounds__(512) void phoneme_proj_kernel(
    const float* __restrict__ pooled, const float* __restrict__ W_in,
    const float* __restrict__ b_in)
{
    __shared__ float sA[32][68];
    __shared__ float sW[32][256];
    int tid = threadIdx.x;
    int r = tid >> 6, cg = tid & 63;
    int row0 = blockIdx.x * 64;
    int fA = tid >> 3, kqA = tid & 7;
    float4 acc[8];
#pragma unroll
    for (int j = 0; j < 8; j++) acc[j] = make_float4(0.f, 0.f, 0.f, 0.f);
    for (int kt = 0; kt < DIN / 32; kt++) {
        __syncthreads();
        float4 av = *(const float4*)(pooled + (size_t)(row0 + fA) * DIN + kt * 32 + kqA * 4);
        sA[kqA * 4 + 0][fA] = av.x; sA[kqA * 4 + 1][fA] = av.y;
        sA[kqA * 4 + 2][fA] = av.z; sA[kqA * 4 + 3][fA] = av.w;
#pragma unroll
        for (int q = 0; q < 4; q++) {
            int e = tid + q * 512;
            int kk = e >> 6, c4 = e & 63;
            *(float4*)&sW[kk][c4 * 4] = *(const float4*)(W_in + (size_t)(kt * 32 + kk) * C_ + c4 * 4);
        }
        __syncthreads();
#pragma unroll
        for (int kk = 0; kk < 32; kk++) {
            float4 a0 = *(const float4*)&sA[kk][r * 8];
            float4 a1 = *(const float4*)&sA[kk][r * 8 + 4];
            float4 w  = *(const float4*)&sW[kk][cg * 4];
            float av4[8] = {a0.x,a0.y,a0.z,a0.w,a1.x,a1.y,a1.z,a1.w};
#pragma unroll
            for (int j = 0; j < 8; j++) {
                acc[j].x = fmaf(av4[j], w.x, acc[j].x);
                acc[j].y = fmaf(av4[j], w.y, acc[j].y);
                acc[j].z = fmaf(av4[j], w.z, acc[j].z);
                acc[j].w = fmaf(av4[j], w.w, acc[j].w);
            }
        }
    }
    float4 bi = *(const float4*)(b_in + cg * 4);
#pragma unroll
    for (int j = 0; j < 8; j++) {
        float4 v = acc[j];
        v.x += bi.x; v.y += bi.y; v.z += bi.z; v.w += bi.w;
        *(float4*)(g_p + (size_t)(row0 + r * 8 + j) * C_ + cg * 4) = v;
    }
}

// ---------------- pos projection + gather-add ----------------
__global__ __launch_bounds__(512) void posproj_kernel(
    const float* __restrict__ rel_pos, const float* __restrict__ W_pos,
    const float* __restrict__ b_pos)
{
    __shared__ float sA[32][68];
    __shared__ float sW[32][256];
    __shared__ float s_rel[64];
    __shared__ float s_freq[128];
    __shared__ int   s_id[64];
    int tid = threadIdx.x;
    int r = tid >> 6, cg = tid & 63;
    int b = blockIdx.y;
    int t0 = blockIdx.x * 64;
    int fA = tid >> 3, kqA = tid & 7;
    if (tid < 64) {
        s_rel[tid] = rel_pos[b * T_ + t0 + tid];
        s_id[tid]  = g_idx[b * T_ + t0 + tid];
    } else if (tid < 192) {
        int j = tid - 64;
        s_freq[j] = expf(-9.210340371976184f * (float)j * (1.0f / 127.0f));
    }
    __syncthreads();
    float4 acc[8];
#pragma unroll
    for (int j = 0; j < 8; j++) acc[j] = make_float4(0.f, 0.f, 0.f, 0.f);
    for (int kt = 0; kt < C_ / 32; kt++) {
        __syncthreads();
        float rv = s_rel[fA];
#pragma unroll
        for (int j = 0; j < 4; j++) {
            int k = kt * 32 + kqA * 4 + j;
            float arg = rv * s_freq[k & 127];
            sA[kqA * 4 + j][fA] = (k < 128) ? sinf(arg) : cosf(arg);
        }
#pragma unroll
        for (int q = 0; q < 4; q++) {
            int e = tid + q * 512;
            int kk = e >> 6, c4 = e & 63;
            *(float4*)&sW[kk][c4 * 4] = *(const float4*)(W_pos + (size_t)(kt * 32 + kk) * C_ + c4 * 4);
        }
        __syncthreads();
#pragma unroll
        for (int kk = 0; kk < 32; kk++) {
            float4 a0 = *(const float4*)&sA[kk][r * 8];
            float4 a1 = *(const float4*)&sA[kk][r * 8 + 4];
            float4 w  = *(const float4*)&sW[kk][cg * 4];
            float av4[8] = {a0.x,a0.y,a0.z,a0.w,a1.x,a1.y,a1.z,a1.w};
#pragma unroll
            for (int j = 0; j < 8; j++) {
                acc[j].x = fmaf(av4[j], w.x, acc[j].x);
                acc[j].y = fmaf(av4[j], w.y, acc[j].y);
                acc[j].z = fmaf(av4[j], w.z, acc[j].z);
                acc[j].w = fmaf(av4[j], w.w, acc[j].w);
            }
        }
    }
    float4 bp = *(const float4*)(b_pos + cg * 4);
#pragma unroll
    for (int j = 0; j < 8; j++) {
        int f = r * 8 + j;
        float4 pv = *(const float4*)(g_p + ((size_t)(b * N_ + s_id[f]) << 8) + cg * 4);
        float4 v = acc[j];
        v.x += bp.x + pv.x; v.y += bp.y + pv.y;
        v.z += bp.z + pv.z; v.w += bp.w + pv.w;
        *(float4*)(g_x + ((size_t)(b * T_ + t0 + f) << 8) + cg * 4) = v;
    }
}

// ---------------- prep: h0 = split(gelu(LN0(x))) ----------------
__device__ __forceinline__ float warp_sum(float v) {
#pragma unroll
    for (int off = 16; off; off >>= 1) v += __shfl_xor_sync(0xffffffffu, v, off);
    return v;
}
__global__ __launch_bounds__(256) void prep_kernel(
    const float* __restrict__ g0, const float* __restrict__ b0)
{
    int warp = threadIdx.x >> 5, lane = threadIdx.x & 31;
    int frame = blockIdx.x * 8 + warp;
    const float* xr = g_x + ((size_t)frame << 8);
    float v[8];
#pragma unroll
    for (int i = 0; i < 8; i++) v[i] = xr[lane + 32 * i];
    float s = 0.f;
#pragma unroll
    for (int i = 0; i < 8; i++) s += v[i];
    float mean = warp_sum(s) * (1.0f / C_);
    float s2 = 0.f;
#pragma unroll
    for (int i = 0; i < 8; i++) { float d = v[i] - mean; s2 += d * d; }
    float rstd = rsqrtf(warp_sum(s2) * (1.0f / C_) + EPS_);
#pragma unroll
    for (int i = 0; i < 8; i++) {
        int ch = lane + 32 * i;
        float y = (v[i] - mean) * rstd * g0[ch] + b0[ch];
        float gl = 0.5f * y * (1.0f + erff(y * 0.70710678118654752f));
        __nv_bfloat16 hi = __float2bfloat16_rn(gl);
        float lo = gl - __bfloat162float(hi);
        size_t id = ((size_t)frame << 8) + ch;
        g_hAh[id] = hi;
        g_hAl[id] = __float2bfloat16_rn(lo);
    }
}

// ---------------- mma.sync conv layer ----------------
// smem layout (dynamic):
//   AH: 158 rows x 528B   [0, 83424)
//   AL: 158 rows x 528B   [83424, 166848)
//   B:  2 stages x (Bh 256x48 | Bl 256x48)  [166848, 216000)
#define AROWB 528
#define AL_OFF 83424
#define B_OFF  166848
#define BSTAGE 24576
#define BLOFF  12288
#define DYN_SMEM 216064
#define NSTEP (K_ * 16)      // 496
#define SB_STRIDE 268        // epilogue sbuf float stride

__device__ __forceinline__ void loadB(uint32_t dbase, int stage, int step, int l) {
    int tid = threadIdx.x;
    int kt = step >> 4, kc = step & 15;
    int z = l * K_ + kt;
    const __nv_bfloat16* srch = g_wh + (((size_t)(z * C_ + tid)) << 8) + kc * 16;
    const __nv_bfloat16* srcl = g_wl + (((size_t)(z * C_ + tid)) << 8) + kc * 16;
    uint32_t brow = dbase + B_OFF + (uint32_t)stage * BSTAGE + (uint32_t)tid * 48;
    cpa16(brow,      srch,     16);
    cpa16(brow + 16, srch + 8, 16);
    cpa16(brow + BLOFF,      srcl,     16);
    cpa16(brow + BLOFF + 16, srcl + 8, 16);
}

__global__ __launch_bounds__(256, 1) void conv_mma_kernel(
    int l, int pp, int last,
    const float* __restrict__ conv_b,
    const float* __restrict__ ng, const float* __restrict__ nb,
    float* __restrict__ outp)
{
    extern __shared__ char dsm[];
    __shared__ float s_cb[C_], s_g[C_], s_b[C_];

    int tid = threadIdx.x;
    int wid = tid >> 5, lane = tid & 31;
    int warpM = wid >> 2, warpN = wid & 3;       // 2 x 4 warp grid
    int b  = blockIdx.x >> 6;
    int t0 = (blockIdx.x & 63) << 7;

    const __nv_bfloat16* hh = pp ? g_hBh : g_hAh;
    const __nv_bfloat16* hl = pp ? g_hBl : g_hAl;
    __nv_bfloat16* dsth = pp ? g_hAh : g_hBh;
    __nv_bfloat16* dstl = pp ? g_hAl : g_hBl;

    uint32_t dbase = smem_u32(dsm);

    if (tid < C_) {
        s_cb[tid] = conv_b[l * C_ + tid];
        s_g[tid]  = ng[tid];
        s_b[tid]  = nb[tid];
    }

    // ---- prologue: A window (158 rows, hi+lo) + B stages 0,1 ----
    for (int e = tid; e < 158 * 32; e += 256) {
        int r = e >> 5, g = e & 31;
        int t = t0 - (K_ - 1) + r;
        int sz = (t >= 0) ? 16 : 0;
        size_t srow = (((size_t)(b * T_ + (t < 0 ? 0 : t))) << 8) + g * 8;
        cpa16(dbase + (uint32_t)r * AROWB + g * 16, hh + srow, sz);
        cpa16(dbase + AL_OFF + (uint32_t)r * AROWB + g * 16, hl + srow, sz);
    }
    loadB(dbase, 0, 0, l);
    CP_COMMIT();                 // group0 = A + B0
    loadB(dbase, 1, 1, l);
    CP_COMMIT();                 // group1 = B1

    float acc[4][8][4];
#pragma unroll
    for (int mi = 0; mi < 4; mi++)
#pragma unroll
        for (int ni = 0; ni < 8; ni++)
#pragma unroll
            for (int q = 0; q < 4; q++) acc[mi][ni][q] = 0.f;

    uint32_t bl_lane = (uint32_t)(((lane & 7) + ((lane >> 4) << 3)) * 48 + (((lane >> 3) & 1) << 4));

    for (int i = 0; i < NSTEP; i++) {
        int s = i & 1;
        CP_WAIT1();
        __syncthreads();

        int kt = i >> 4, kc = i & 15;
        uint32_t abase = dbase
            + (uint32_t)(kt + warpM * 64 + (lane & 15)) * AROWB
            + (uint32_t)(kc * 16 + ((lane >> 4) << 3)) * 2;

        uint32_t ah[4][4], al[4][4];
#pragma unroll
        for (int mi = 0; mi < 4; mi++) {
            ldsm4(ah[mi], abase + mi * 16 * AROWB);
            ldsm4(al[mi], abase + AL_OFF + mi * 16 * AROWB);
        }
        uint32_t bs = dbase + B_OFF + (uint32_t)s * BSTAGE;
        uint32_t bb[8][2];
#pragma unroll
        for (int nq = 0; nq < 4; nq++) {
            uint32_t r4[4];
            ldsm4(r4, bs + (uint32_t)(warpN * 64 + nq * 16) * 48 + bl_lane);
            bb[nq * 2][0] = r4[0]; bb[nq * 2][1] = r4[1];
            bb[nq * 2 + 1][0] = r4[2]; bb[nq * 2 + 1][1] = r4[3];
        }
        // pass 1: Ah x Bh
#pragma unroll
        for (int mi = 0; mi < 4; mi++)
#pragma unroll
            for (int ni = 0; ni < 8; ni++)
                mma16816(acc[mi][ni], ah[mi], bb[ni]);
        // pass 2: Al x Bh
#pragma unroll
        for (int mi = 0; mi < 4; mi++)
#pragma unroll
            for (int ni = 0; ni < 8; ni++)
                mma16816(acc[mi][ni], al[mi], bb[ni]);
        // pass 3: Ah x Bl
#pragma unroll
        for (int nq = 0; nq < 4; nq++) {
            uint32_t r4[4];
            ldsm4(r4, bs + BLOFF + (uint32_t)(warpN * 64 + nq * 16) * 48 + bl_lane);
            bb[nq * 2][0] = r4[0]; bb[nq * 2][1] = r4[1];
            bb[nq * 2 + 1][0] = r4[2]; bb[nq * 2 + 1][1] = r4[3];
        }
#pragma unroll
        for (int mi = 0; mi < 4; mi++)
#pragma unroll
            for (int ni = 0; ni < 8; ni++)
                mma16816(acc[mi][ni], ah[mi], bb[ni]);

        __syncthreads();
        if (i + 2 < NSTEP) loadB(dbase, s, i + 2, l);
        CP_COMMIT();
    }
    __syncthreads();

    // ---- epilogue: acc -> smem (aliases A region), then fused LN ----
    float* sbuf = (float*)dsm;   // [128][SB_STRIDE]
#pragma unroll
    for (int mi = 0; mi < 4; mi++)
#pragma unroll
        for (int ni = 0; ni < 8; ni++) {
            int r0 = warpM * 64 + mi * 16 + (lane >> 2);
            int col = warpN * 64 + ni * 8 + ((lane & 3) << 1);
            *(float2*)&sbuf[r0 * SB_STRIDE + col] =
                make_float2(acc[mi][ni][0], acc[mi][ni][1]);
            *(float2*)&sbuf[(r0 + 8) * SB_STRIDE + col] =
                make_float2(acc[mi][ni][2], acc[mi][ni][3]);
        }
    __syncthreads();

    for (int f0 = 0; f0 < 16; f0++) {
        int f = wid * 16 + f0;
        size_t rowid = ((size_t)(b * T_ + t0 + f)) << 8;
        int c0 = lane * 8;
        float4 u0 = *(float4*)&sbuf[f * SB_STRIDE + c0];
        float4 u1 = *(float4*)&sbuf[f * SB_STRIDE + c0 + 4];
        float4 x0 = *(const float4*)(g_x + rowid + c0);
        float4 x1 = *(const float4*)(g_x + rowid + c0 + 4);
        float y[8];
        y[0] = u0.x + x0.x + s_cb[c0 + 0]; y[1] = u0.y + x0.y + s_cb[c0 + 1];
        y[2] = u0.z + x0.z + s_cb[c0 + 2]; y[3] = u0.w + x0.w + s_cb[c0 + 3];
        y[4] = u1.x + x1.x + s_cb[c0 + 4]; y[5] = u1.y + x1.y + s_cb[c0 + 5];
        y[6] = u1.z + x1.z + s_cb[c0 + 6]; y[7] = u1.w + x1.w + s_cb[c0 + 7];
        float sum = 0.f, sq = 0.f;
#pragma unroll
        for (int j = 0; j < 8; j++) { sum += y[j]; sq += y[j] * y[j]; }
        float mu = warp_sum(sum) * (1.f / C_);
        float rs = rsqrtf(warp_sum(sq) * (1.f / C_) - mu * mu + EPS_);
        float z[8];
#pragma unroll
        for (int j = 0; j < 8; j++)
            z[j] = (y[j] - mu) * rs * s_g[c0 + j] + s_b[c0 + j];
        if (last) {
            float4 o0 = {z[0], z[1], z[2], z[3]};
            float4 o1 = {z[4], z[5], z[6], z[7]};
            *(float4*)(outp + rowid + c0)     = o0;
            *(float4*)(outp + rowid + c0 + 4) = o1;
        } else {
            float4 y0 = {y[0], y[1], y[2], y[3]};
            float4 y1 = {y[4], y[5], y[6], y[7]};
            *(float4*)(g_x + rowid + c0)     = y0;
            *(float4*)(g_x + rowid + c0 + 4) = y1;
            __nv_bfloat16 hv[8], lv[8];
#pragma unroll
            for (int j = 0; j < 8; j++) {
                float gl = 0.5f * z[j] * (1.0f + erff(z[j] * 0.70710678118654752f));
                hv[j] = __float2bfloat16_rn(gl);
                lv[j] = __float2bfloat16_rn(gl - __bfloat162float(hv[j]));
            }
#pragma unroll
            for (int j = 0; j < 4; j++) {
                __nv_bfloat162 h2 = {hv[2 * j], hv[2 * j + 1]};
                __nv_bfloat162 l2 = {lv[2 * j], lv[2 * j + 1]};
                *(__nv_bfloat162*)(dsth + rowid + c0 + 2 * j) = h2;
                *(__nv_bfloat162*)(dstl + rowid + c0 + 2 * j) = l2;
            }
        }
    }
}

// ---------------------------------------------------------------------------
extern "C" void kernel_launch(void* const* d_in, const int* in_sizes, int n_in,
                              void* d_out, int out_size)
{
    const float* pooled    = (const float*)d_in[0];
    const int*   durations = (const int*)  d_in[1];
    const float* rel_pos   = (const float*)d_in[2];
    const float* W_in      = (const float*)d_in[3];
    const float* b_in      = (const float*)d_in[4];
    const float* W_pos     = (const float*)d_in[5];
    const float* b_pos     = (const float*)d_in[6];
    const float* ln_g      = (const float*)d_in[7];
    const float* ln_b      = (const float*)d_in[8];
    const float* conv_w    = (const float*)d_in[9];
    const float* conv_b    = (const float*)d_in[10];
    const float* out_g     = (const float*)d_in[11];
    const float* out_b     = (const float*)d_in[12];
    float* out = (float*)d_out;

    cudaFuncSetAttribute(conv_mma_kernel,
                         cudaFuncAttributeMaxDynamicSharedMemorySize, DYN_SMEM);

    idx_kernel<<<B_, 256>>>(durations);
    wsplit_kernel<<<NZ * C_, 256>>>(conv_w);
    phoneme_proj_kernel<<<B_ * N_ / 64, 512>>>(pooled, W_in, b_in);
    posproj_kernel<<<dim3(T_ / 64, B_), 512>>>(rel_pos, W_pos, b_pos);
    prep_kernel<<<B_ * T_ / 8, 256>>>(ln_g, ln_b);

    conv_mma_kernel<<<B_ * T_ / 128, 256, DYN_SMEM>>>(
        0, 0, 0, conv_b, ln_g + C_, ln_b + C_, out);
    conv_mma_kernel<<<B_ * T_ / 128, 256, DYN_SMEM>>>(
        1, 1, 0, conv_b, ln_g + 2 * C_, ln_b + 2 * C_, out);
    conv_mma_kernel<<<B_ * T_ / 128, 256, DYN_SMEM>>>(
        2, 0, 1, conv_b, out_g, out_b, out);
}

// round 15
// speedup vs baseline: 31.4678x; 1.3871x over previous
#include <cuda_runtime.h>
#include <cuda_bf16.h>
#include <cuda_fp16.h>
#include <cstdint>
#include <stdint.h>
#include <math.h>

#define B_ 8
#define N_ 1024
#define DIN 512
#define C_ 256
#define T_ 8192
#define K_ 31
#define L_ 3
#define EPS_ 1e-5f
#define NZ (L_ * K_)

// device scratch (allocation-free rule)
__device__ __align__(1024) float g_x[B_ * T_ * C_];
__device__ __align__(1024) float g_p[B_ * N_ * C_];
__device__ __align__(1024) __half g_hAh[B_ * T_ * C_];
__device__ __align__(1024) __half g_hAl[B_ * T_ * C_];
__device__ __align__(1024) __half g_hBh[B_ * T_ * C_];
__device__ __align__(1024) __half g_hBl[B_ * T_ * C_];
__device__ __align__(1024) __half g_wh[NZ * C_ * C_];
__device__ int g_idx[B_ * T_];

// ---------------- PTX helpers ----------------
__device__ __forceinline__ uint32_t smem_u32(const void* p) {
    uint32_t a;
    asm("{ .reg .u64 t; cvta.to.shared.u64 t, %1; cvt.u32.u64 %0, t; }" : "=r"(a) : "l"(p));
    return a;
}
__device__ __forceinline__ void cpa16(uint32_t dst, const void* src, int sz) {
    asm volatile("cp.async.cg.shared.global [%0], [%1], 16, %2;"
                 :: "r"(dst), "l"(src), "r"(sz) : "memory");
}
#define CP_COMMIT() asm volatile("cp.async.commit_group;" ::: "memory")
#define CP_WAIT1()  asm volatile("cp.async.wait_group 1;" ::: "memory")

__device__ __forceinline__ void ldsm4(uint32_t* r, uint32_t a) {
    asm volatile("ldmatrix.sync.aligned.m8n8.x4.shared.b16 {%0,%1,%2,%3}, [%4];"
        : "=r"(r[0]), "=r"(r[1]), "=r"(r[2]), "=r"(r[3]) : "r"(a));
}
__device__ __forceinline__ void mma16816(float* c, const uint32_t* a, const uint32_t* b) {
    asm volatile("mma.sync.aligned.m16n8k16.row.col.f32.f16.f16.f32 "
        "{%0,%1,%2,%3}, {%4,%5,%6,%7}, {%8,%9}, {%0,%1,%2,%3};"
        : "+f"(c[0]), "+f"(c[1]), "+f"(c[2]), "+f"(c[3])
        : "r"(a[0]), "r"(a[1]), "r"(a[2]), "r"(a[3]), "r"(b[0]), "r"(b[1]));
}

// ---------------- idx kernel ----------------
__global__ __launch_bounds__(256) void idx_kernel(const int* __restrict__ durations) {
    __shared__ int cum[N_];
    __shared__ int wsum[8];
    int b = blockIdx.x, tid = threadIdx.x;
    int lane = tid & 31, warp = tid >> 5;
    int d[4], inc[4];
    int s = 0;
#pragma unroll
    for (int i = 0; i < 4; i++) { d[i] = durations[b * N_ + tid * 4 + i]; s += d[i]; inc[i] = s; }
    int x = s;
#pragma unroll
    for (int off = 1; off < 32; off <<= 1) {
        int y = __shfl_up_sync(0xffffffffu, x, off);
        if (lane >= off) x += y;
    }
    if (lane == 31) wsum[warp] = x;
    __syncthreads();
    if (tid == 0) {
        int acc = 0;
#pragma unroll
        for (int w = 0; w < 8; w++) { int v = wsum[w]; wsum[w] = acc; acc += v; }
    }
    __syncthreads();
    int excl = wsum[warp] + (x - s);
#pragma unroll
    for (int i = 0; i < 4; i++) cum[tid * 4 + i] = excl + inc[i];
    __syncthreads();
    for (int t = tid; t < T_; t += 256) {
        int lo = 0, hi = N_ - 1;
        while (lo < hi) { int m = (lo + hi) >> 1; if (cum[m] > t) hi = m; else lo = m + 1; }
        g_idx[b * T_ + t] = lo;
    }
}

// ---------------- weights: conv_w[l][o][i][k] -> fp16 [z][o][i] -------------
__global__ __launch_bounds__(256) void wsplit_kernel(const float* __restrict__ cw) {
    int blk = blockIdx.x;                 // z*256 + o
    int o = blk & 255, z = blk >> 8;
    int l = z / K_, k = z - l * K_;
    int i = threadIdx.x;
    float w = cw[((size_t)((l * C_ + o) * C_ + i)) * K_ + k];
    g_wh[((size_t)z * C_ + o) * C_ + i] = __float2half_rn(w);
}

// ---------------- phoneme projection GEMM ----------------
__global__ __launch_bounds__(512) void phoneme_proj_kernel(
    const float* __restrict__ pooled, const float* __restrict__ W_in,
    const float* __restrict__ b_in)
{
    __shared__ float sA[32][68];
    __shared__ float sW[32][256];
    int tid = threadIdx.x;
    int r = tid >> 6, cg = tid & 63;
    int row0 = blockIdx.x * 64;
    int fA = tid >> 3, kqA = tid & 7;
    float4 acc[8];
#pragma unroll
    for (int j = 0; j < 8; j++) acc[j] = make_float4(0.f, 0.f, 0.f, 0.f);
    for (int kt = 0; kt < DIN / 32; kt++) {
        __syncthreads();
        float4 av = *(const float4*)(pooled + (size_t)(row0 + fA) * DIN + kt * 32 + kqA * 4);
        sA[kqA * 4 + 0][fA] = av.x; sA[kqA * 4 + 1][fA] = av.y;
        sA[kqA * 4 + 2][fA] = av.z; sA[kqA * 4 + 3][fA] = av.w;
#pragma unroll
        for (int q = 0; q < 4; q++) {
            int e = tid + q * 512;
            int kk = e >> 6, c4 = e & 63;
            *(float4*)&sW[kk][c4 * 4] = *(const float4*)(W_in + (size_t)(kt * 32 + kk) * C_ + c4 * 4);
        }
        __syncthreads();
#pragma unroll
        for (int kk = 0; kk < 32; kk++) {
            float4 a0 = *(const float4*)&sA[kk][r * 8];
            float4 a1 = *(const float4*)&sA[kk][r * 8 + 4];
            float4 w  = *(const float4*)&sW[kk][cg * 4];
            float av4[8] = {a0.x,a0.y,a0.z,a0.w,a1.x,a1.y,a1.z,a1.w};
#pragma unroll
            for (int j = 0; j < 8; j++) {
                acc[j].x = fmaf(av4[j], w.x, acc[j].x);
                acc[j].y = fmaf(av4[j], w.y, acc[j].y);
                acc[j].z = fmaf(av4[j], w.z, acc[j].z);
                acc[j].w = fmaf(av4[j], w.w, acc[j].w);
            }
        }
    }
    float4 bi = *(const float4*)(b_in + cg * 4);
#pragma unroll
    for (int j = 0; j < 8; j++) {
        float4 v = acc[j];
        v.x += bi.x; v.y += bi.y; v.z += bi.z; v.w += bi.w;
        *(float4*)(g_p + (size_t)(row0 + r * 8 + j) * C_ + cg * 4) = v;
    }
}

// ---------------- pos projection + gather-add ----------------
__global__ __launch_bounds__(512) void posproj_kernel(
    const float* __restrict__ rel_pos, const float* __restrict__ W_pos,
    const float* __restrict__ b_pos)
{
    __shared__ float sA[32][68];
    __shared__ float sW[32][256];
    __shared__ float s_rel[64];
    __shared__ float s_freq[128];
    __shared__ int   s_id[64];
    int tid = threadIdx.x;
    int r = tid >> 6, cg = tid & 63;
    int b = blockIdx.y;
    int t0 = blockIdx.x * 64;
    int fA = tid >> 3, kqA = tid & 7;
    if (tid < 64) {
        s_rel[tid] = rel_pos[b * T_ + t0 + tid];
        s_id[tid]  = g_idx[b * T_ + t0 + tid];
    } else if (tid < 192) {
        int j = tid - 64;
        s_freq[j] = expf(-9.210340371976184f * (float)j * (1.0f / 127.0f));
    }
    __syncthreads();
    float4 acc[8];
#pragma unroll
    for (int j = 0; j < 8; j++) acc[j] = make_float4(0.f, 0.f, 0.f, 0.f);
    for (int kt = 0; kt < C_ / 32; kt++) {
        __syncthreads();
        float rv = s_rel[fA];
#pragma unroll
        for (int j = 0; j < 4; j++) {
            int k = kt * 32 + kqA * 4 + j;
            float arg = rv * s_freq[k & 127];
            sA[kqA * 4 + j][fA] = (k < 128) ? sinf(arg) : cosf(arg);
        }
#pragma unroll
        for (int q = 0; q < 4; q++) {
            int e = tid + q * 512;
            int kk = e >> 6, c4 = e & 63;
            *(float4*)&sW[kk][c4 * 4] = *(const float4*)(W_pos + (size_t)(kt * 32 + kk) * C_ + c4 * 4);
        }
        __syncthreads();
#pragma unroll
        for (int kk = 0; kk < 32; kk++) {
            float4 a0 = *(const float4*)&sA[kk][r * 8];
            float4 a1 = *(const float4*)&sA[kk][r * 8 + 4];
            float4 w  = *(const float4*)&sW[kk][cg * 4];
            float av4[8] = {a0.x,a0.y,a0.z,a0.w,a1.x,a1.y,a1.z,a1.w};
#pragma unroll
            for (int j = 0; j < 8; j++) {
                acc[j].x = fmaf(av4[j], w.x, acc[j].x);
                acc[j].y = fmaf(av4[j], w.y, acc[j].y);
                acc[j].z = fmaf(av4[j], w.z, acc[j].z);
                acc[j].w = fmaf(av4[j], w.w, acc[j].w);
            }
        }
    }
    float4 bp = *(const float4*)(b_pos + cg * 4);
#pragma unroll
    for (int j = 0; j < 8; j++) {
        int f = r * 8 + j;
        float4 pv = *(const float4*)(g_p + ((size_t)(b * N_ + s_id[f]) << 8) + cg * 4);
        float4 v = acc[j];
        v.x += bp.x + pv.x; v.y += bp.y + pv.y;
        v.z += bp.z + pv.z; v.w += bp.w + pv.w;
        *(float4*)(g_x + ((size_t)(b * T_ + t0 + f) << 8) + cg * 4) = v;
    }
}

// ---------------- prep: h0 = fp16split(gelu(LN0(x))) ----------------
__device__ __forceinline__ float warp_sum(float v) {
#pragma unroll
    for (int off = 16; off; off >>= 1) v += __shfl_xor_sync(0xffffffffu, v, off);
    return v;
}
__global__ __launch_bounds__(256) void prep_kernel(
    const float* __restrict__ g0, const float* __restrict__ b0)
{
    int warp = threadIdx.x >> 5, lane = threadIdx.x & 31;
    int frame = blockIdx.x * 8 + warp;
    const float* xr = g_x + ((size_t)frame << 8);
    float v[8];
#pragma unroll
    for (int i = 0; i < 8; i++) v[i] = xr[lane + 32 * i];
    float s = 0.f;
#pragma unroll
    for (int i = 0; i < 8; i++) s += v[i];
    float mean = warp_sum(s) * (1.0f / C_);
    float s2 = 0.f;
#pragma unroll
    for (int i = 0; i < 8; i++) { float d = v[i] - mean; s2 += d * d; }
    float rstd = rsqrtf(warp_sum(s2) * (1.0f / C_) + EPS_);
#pragma unroll
    for (int i = 0; i < 8; i++) {
        int ch = lane + 32 * i;
        float y = (v[i] - mean) * rstd * g0[ch] + b0[ch];
        float gl = 0.5f * y * (1.0f + erff(y * 0.70710678118654752f));
        __half hi = __float2half_rn(gl);
        float lo = gl - __half2float(hi);
        size_t id = ((size_t)frame << 8) + ch;
        g_hAh[id] = hi;
        g_hAl[id] = __float2half_rn(lo);
    }
}

// ---------------- mma.sync conv layer (fp16, 2-pass, K=32 steps) ------------
// smem layout (dynamic):
//   AH: 158 rows x 528B   [0, 83424)
//   AL: 158 rows x 528B   [83424, 166848)
//   B:  2 stages x 16384B (256 rows x 64B)  [166848, 199616)
#define AROWB 528
#define AL_OFF 83424
#define B_OFF  166848
#define BSTAGE 16384
#define DYN_SMEM 199680
#define NSTEP (K_ * 8)       // 248 (K=32 per step)
#define SB_STRIDE 268        // epilogue sbuf float stride

__device__ __forceinline__ void loadB(uint32_t dbase, int stage, int step, int l) {
    int tid = threadIdx.x;
    int kt = step >> 3, kc32 = step & 7;
    int z = l * K_ + kt;
    const __half* src = g_wh + (((size_t)(z * C_ + tid)) << 8) + kc32 * 32;
    uint32_t brow = dbase + B_OFF + (uint32_t)stage * BSTAGE + (uint32_t)tid * 64;
#pragma unroll
    for (int q = 0; q < 4; q++)
        cpa16(brow + q * 16, src + q * 8, 16);
}

__global__ __launch_bounds__(256, 1) void conv_mma_kernel(
    int l, int pp, int last,
    const float* __restrict__ conv_b,
    const float* __restrict__ ng, const float* __restrict__ nb,
    float* __restrict__ outp)
{
    extern __shared__ char dsm[];
    __shared__ float s_cb[C_], s_g[C_], s_b[C_];

    int tid = threadIdx.x;
    int wid = tid >> 5, lane = tid & 31;
    int warpM = wid >> 2, warpN = wid & 3;       // 2 x 4 warp grid
    int b  = blockIdx.x >> 6;
    int t0 = (blockIdx.x & 63) << 7;

    const __half* hh = pp ? g_hBh : g_hAh;
    const __half* hl = pp ? g_hBl : g_hAl;
    __half* dsth = pp ? g_hAh : g_hBh;
    __half* dstl = pp ? g_hAl : g_hBl;

    uint32_t dbase = smem_u32(dsm);

    if (tid < C_) {
        s_cb[tid] = conv_b[l * C_ + tid];
        s_g[tid]  = ng[tid];
        s_b[tid]  = nb[tid];
    }

    // ---- prologue: A window (158 rows, hi+lo) + B stages 0,1 ----
    for (int e = tid; e < 158 * 32; e += 256) {
        int r = e >> 5, g = e & 31;
        int t = t0 - (K_ - 1) + r;
        int sz = (t >= 0) ? 16 : 0;
        size_t srow = (((size_t)(b * T_ + (t < 0 ? 0 : t))) << 8) + g * 8;
        cpa16(dbase + (uint32_t)r * AROWB + g * 16, hh + srow, sz);
        cpa16(dbase + AL_OFF + (uint32_t)r * AROWB + g * 16, hl + srow, sz);
    }
    loadB(dbase, 0, 0, l);
    CP_COMMIT();                 // group0 = A + B0
    loadB(dbase, 1, 1, l);
    CP_COMMIT();                 // group1 = B1

    float acc[4][8][4];
#pragma unroll
    for (int mi = 0; mi < 4; mi++)
#pragma unroll
        for (int ni = 0; ni < 8; ni++)
#pragma unroll
            for (int q = 0; q < 4; q++) acc[mi][ni][q] = 0.f;

    uint32_t bl_lane = (uint32_t)(((lane & 7) + ((lane >> 4) << 3)) * 64 + (((lane >> 3) & 1) << 4));

    for (int i = 0; i < NSTEP; i++) {
        int s = i & 1;
        CP_WAIT1();
        __syncthreads();

        int kt = i >> 3, kc32 = i & 7;
        uint32_t bs = dbase + B_OFF + (uint32_t)s * BSTAGE;

#pragma unroll
        for (int kc2 = 0; kc2 < 2; kc2++) {
            int kc = kc32 * 2 + kc2;
            uint32_t abase = dbase
                + (uint32_t)(kt + warpM * 64 + (lane & 15)) * AROWB
                + (uint32_t)(kc * 16 + ((lane >> 4) << 3)) * 2;

            uint32_t ah[4][4], al[4][4];
#pragma unroll
            for (int mi = 0; mi < 4; mi++) {
                ldsm4(ah[mi], abase + mi * 16 * AROWB);
                ldsm4(al[mi], abase + AL_OFF + mi * 16 * AROWB);
            }
            uint32_t bb[8][2];
#pragma unroll
            for (int nq = 0; nq < 4; nq++) {
                uint32_t r4[4];
                ldsm4(r4, bs + (uint32_t)(warpN * 64 + nq * 16) * 64 + kc2 * 32 + bl_lane);
                bb[nq * 2][0] = r4[0]; bb[nq * 2][1] = r4[1];
                bb[nq * 2 + 1][0] = r4[2]; bb[nq * 2 + 1][1] = r4[3];
            }
            // pass 1: Ah x B
#pragma unroll
            for (int mi = 0; mi < 4; mi++)
#pragma unroll
                for (int ni = 0; ni < 8; ni++)
                    mma16816(acc[mi][ni], ah[mi], bb[ni]);
            // pass 2: Al x B
#pragma unroll
            for (int mi = 0; mi < 4; mi++)
#pragma unroll
                for (int ni = 0; ni < 8; ni++)
                    mma16816(acc[mi][ni], al[mi], bb[ni]);
        }

        __syncthreads();
        if (i + 2 < NSTEP) loadB(dbase, s, i + 2, l);
        CP_COMMIT();
    }
    __syncthreads();

    // ---- epilogue: acc -> smem (aliases A region), then fused LN ----
    float* sbuf = (float*)dsm;   // [128][SB_STRIDE]
#pragma unroll
    for (int mi = 0; mi < 4; mi++)
#pragma unroll
        for (int ni = 0; ni < 8; ni++) {
            int r0 = warpM * 64 + mi * 16 + (lane >> 2);
            int col = warpN * 64 + ni * 8 + ((lane & 3) << 1);
            *(float2*)&sbuf[r0 * SB_STRIDE + col] =
                make_float2(acc[mi][ni][0], acc[mi][ni][1]);
            *(float2*)&sbuf[(r0 + 8) * SB_STRIDE + col] =
                make_float2(acc[mi][ni][2], acc[mi][ni][3]);
        }
    __syncthreads();

    for (int f0 = 0; f0 < 16; f0++) {
        int f = wid * 16 + f0;
        size_t rowid = ((size_t)(b * T_ + t0 + f)) << 8;
        int c0 = lane * 8;
        float4 u0 = *(float4*)&sbuf[f * SB_STRIDE + c0];
        float4 u1 = *(float4*)&sbuf[f * SB_STRIDE + c0 + 4];
        float4 x0 = *(const float4*)(g_x + rowid + c0);
        float4 x1 = *(const float4*)(g_x + rowid + c0 + 4);
        float y[8];
        y[0] = u0.x + x0.x + s_cb[c0 + 0]; y[1] = u0.y + x0.y + s_cb[c0 + 1];
        y[2] = u0.z + x0.z + s_cb[c0 + 2]; y[3] = u0.w + x0.w + s_cb[c0 + 3];
        y[4] = u1.x + x1.x + s_cb[c0 + 4]; y[5] = u1.y + x1.y + s_cb[c0 + 5];
        y[6] = u1.z + x1.z + s_cb[c0 + 6]; y[7] = u1.w + x1.w + s_cb[c0 + 7];
        float sum = 0.f, sq = 0.f;
#pragma unroll
        for (int j = 0; j < 8; j++) { sum += y[j]; sq += y[j] * y[j]; }
        float mu = warp_sum(sum) * (1.f / C_);
        float rs = rsqrtf(warp_sum(sq) * (1.f / C_) - mu * mu + EPS_);
        float z[8];
#pragma unroll
        for (int j = 0; j < 8; j++)
            z[j] = (y[j] - mu) * rs * s_g[c0 + j] + s_b[c0 + j];
        if (last) {
            float4 o0 = {z[0], z[1], z[2], z[3]};
            float4 o1 = {z[4], z[5], z[6], z[7]};
            *(float4*)(outp + rowid + c0)     = o0;
            *(float4*)(outp + rowid + c0 + 4) = o1;
        } else {
            float4 y0 = {y[0], y[1], y[2], y[3]};
            float4 y1 = {y[4], y[5], y[6], y[7]};
            *(float4*)(g_x + rowid + c0)     = y0;
            *(float4*)(g_x + rowid + c0 + 4) = y1;
            __half hv[8], lv[8];
#pragma unroll
            for (int j = 0; j < 8; j++) {
                float gl = 0.5f * z[j] * (1.0f + erff(z[j] * 0.70710678118654752f));
                hv[j] = __float2half_rn(gl);
                lv[j] = __float2half_rn(gl - __half2float(hv[j]));
            }
#pragma unroll
            for (int j = 0; j < 4; j++) {
                __half2 h2 = {hv[2 * j], hv[2 * j + 1]};
                __half2 l2 = {lv[2 * j], lv[2 * j + 1]};
                *(__half2*)(dsth + rowid + c0 + 2 * j) = h2;
                *(__half2*)(dstl + rowid + c0 + 2 * j) = l2;
            }
        }
    }
}

// ---------------------------------------------------------------------------
extern "C" void kernel_launch(void* const* d_in, const int* in_sizes, int n_in,
                              void* d_out, int out_size)
{
    const float* pooled    = (const float*)d_in[0];
    const int*   durations = (const int*)  d_in[1];
    const float* rel_pos   = (const float*)d_in[2];
    const float* W_in      = (const float*)d_in[3];
    const float* b_in      = (const float*)d_in[4];
    const float* W_pos     = (const float*)d_in[5];
    const float* b_pos     = (const float*)d_in[6];
    const float* ln_g      = (const float*)d_in[7];
    const float* ln_b      = (const float*)d_in[8];
    const float* conv_w    = (const float*)d_in[9];
    const float* conv_b    = (const float*)d_in[10];
    const float* out_g     = (const float*)d_in[11];
    const float* out_b     = (const float*)d_in[12];
    float* out = (float*)d_out;

    cudaFuncSetAttribute(conv_mma_kernel,
                         cudaFuncAttributeMaxDynamicSharedMemorySize, DYN_SMEM);

    idx_kernel<<<B_, 256>>>(durations);
    wsplit_kernel<<<NZ * C_, 256>>>(conv_w);
    phoneme_proj_kernel<<<B_ * N_ / 64, 512>>>(pooled, W_in, b_in);
    posproj_kernel<<<dim3(T_ / 64, B_), 512>>>(rel_pos, W_pos, b_pos);
    prep_kernel<<<B_ * T_ / 8, 256>>>(ln_g, ln_b);

    conv_mma_kernel<<<B_ * T_ / 128, 256, DYN_SMEM>>>(
        0, 0, 0, conv_b, ln_g + C_, ln_b + C_, out);
    conv_mma_kernel<<<B_ * T_ / 128, 256, DYN_SMEM>>>(
        1, 1, 0, conv_b, ln_g + 2 * C_, ln_b + 2 * C_, out);
    conv_mma_kernel<<<B_ * T_ / 128, 256, DYN_SMEM>>>(
        2, 0, 1, conv_b, out_g, out_b, out);
}

// round 16
// speedup vs baseline: 47.0898x; 1.4964x over previous
#include <cuda_runtime.h>
#include <cuda_fp16.h>
#include <cstdint>
#include <stdint.h>
#include <math.h>

#define B_ 8
#define N_ 1024
#define DIN 512
#define C_ 256
#define T_ 8192
#define K_ 31
#define L_ 3
#define EPS_ 1e-5f
#define NZ (L_ * K_)

// device scratch (allocation-free rule)
__device__ __align__(1024) float g_x[B_ * T_ * C_];
__device__ __align__(1024) float g_p[B_ * N_ * C_];
__device__ __align__(1024) __half g_hA[B_ * T_ * C_];
__device__ __align__(1024) __half g_hB[B_ * T_ * C_];
__device__ __align__(1024) __half g_wh[NZ * C_ * C_];
__device__ int g_idx[B_ * T_];

// ---------------- PTX helpers ----------------
__device__ __forceinline__ uint32_t smem_u32(const void* p) {
    uint32_t a;
    asm("{ .reg .u64 t; cvta.to.shared.u64 t, %1; cvt.u32.u64 %0, t; }" : "=r"(a) : "l"(p));
    return a;
}
__device__ __forceinline__ void cpa16(uint32_t dst, const void* src, int sz) {
    asm volatile("cp.async.cg.shared.global [%0], [%1], 16, %2;"
                 :: "r"(dst), "l"(src), "r"(sz) : "memory");
}
#define CP_COMMIT() asm volatile("cp.async.commit_group;" ::: "memory")
#define CP_WAIT1()  asm volatile("cp.async.wait_group 1;" ::: "memory")

__device__ __forceinline__ void ldsm4(uint32_t* r, uint32_t a) {
    asm volatile("ldmatrix.sync.aligned.m8n8.x4.shared.b16 {%0,%1,%2,%3}, [%4];"
        : "=r"(r[0]), "=r"(r[1]), "=r"(r[2]), "=r"(r[3]) : "r"(a));
}
__device__ __forceinline__ void mma16816(float* c, const uint32_t* a, const uint32_t* b) {
    asm volatile("mma.sync.aligned.m16n8k16.row.col.f32.f16.f16.f32 "
        "{%0,%1,%2,%3}, {%4,%5,%6,%7}, {%8,%9}, {%0,%1,%2,%3};"
        : "+f"(c[0]), "+f"(c[1]), "+f"(c[2]), "+f"(c[3])
        : "r"(a[0]), "r"(a[1]), "r"(a[2]), "r"(a[3]), "r"(b[0]), "r"(b[1]));
}

// ---------------- idx kernel ----------------
__global__ __launch_bounds__(256) void idx_kernel(const int* __restrict__ durations) {
    __shared__ int cum[N_];
    __shared__ int wsum[8];
    int b = blockIdx.x, tid = threadIdx.x;
    int lane = tid & 31, warp = tid >> 5;
    int d[4], inc[4];
    int s = 0;
#pragma unroll
    for (int i = 0; i < 4; i++) { d[i] = durations[b * N_ + tid * 4 + i]; s += d[i]; inc[i] = s; }
    int x = s;
#pragma unroll
    for (int off = 1; off < 32; off <<= 1) {
        int y = __shfl_up_sync(0xffffffffu, x, off);
        if (lane >= off) x += y;
    }
    if (lane == 31) wsum[warp] = x;
    __syncthreads();
    if (tid == 0) {
        int acc = 0;
#pragma unroll
        for (int w = 0; w < 8; w++) { int v = wsum[w]; wsum[w] = acc; acc += v; }
    }
    __syncthreads();
    int excl = wsum[warp] + (x - s);
#pragma unroll
    for (int i = 0; i < 4; i++) cum[tid * 4 + i] = excl + inc[i];
    __syncthreads();
    for (int t = tid; t < T_; t += 256) {
        int lo = 0, hi = N_ - 1;
        while (lo < hi) { int m = (lo + hi) >> 1; if (cum[m] > t) hi = m; else lo = m + 1; }
        g_idx[b * T_ + t] = lo;
    }
}

// ---------------- weights: conv_w[l][o][i][k] -> fp16 [z][o][i] -------------
__global__ __launch_bounds__(256) void wsplit_kernel(const float* __restrict__ cw) {
    int blk = blockIdx.x;                 // z*256 + o
    int o = blk & 255, z = blk >> 8;
    int l = z / K_, k = z - l * K_;
    int i = threadIdx.x;
    float w = cw[((size_t)((l * C_ + o) * C_ + i)) * K_ + k];
    g_wh[((size_t)z * C_ + o) * C_ + i] = __float2half_rn(w);
}

// ---------------- phoneme projection GEMM ----------------
__global__ __launch_bounds__(512) void phoneme_proj_kernel(
    const float* __restrict__ pooled, const float* __restrict__ W_in,
    const float* __restrict__ b_in)
{
    __shared__ float sA[32][68];
    __shared__ float sW[32][256];
    int tid = threadIdx.x;
    int r = tid >> 6, cg = tid & 63;
    int row0 = blockIdx.x * 64;
    int fA = tid >> 3, kqA = tid & 7;
    float4 acc[8];
#pragma unroll
    for (int j = 0; j < 8; j++) acc[j] = make_float4(0.f, 0.f, 0.f, 0.f);
    for (int kt = 0; kt < DIN / 32; kt++) {
        __syncthreads();
        float4 av = *(const float4*)(pooled + (size_t)(row0 + fA) * DIN + kt * 32 + kqA * 4);
        sA[kqA * 4 + 0][fA] = av.x; sA[kqA * 4 + 1][fA] = av.y;
        sA[kqA * 4 + 2][fA] = av.z; sA[kqA * 4 + 3][fA] = av.w;
#pragma unroll
        for (int q = 0; q < 4; q++) {
            int e = tid + q * 512;
            int kk = e >> 6, c4 = e & 63;
            *(float4*)&sW[kk][c4 * 4] = *(const float4*)(W_in + (size_t)(kt * 32 + kk) * C_ + c4 * 4);
        }
        __syncthreads();
#pragma unroll
        for (int kk = 0; kk < 32; kk++) {
            float4 a0 = *(const float4*)&sA[kk][r * 8];
            float4 a1 = *(const float4*)&sA[kk][r * 8 + 4];
            float4 w  = *(const float4*)&sW[kk][cg * 4];
            float av4[8] = {a0.x,a0.y,a0.z,a0.w,a1.x,a1.y,a1.z,a1.w};
#pragma unroll
            for (int j = 0; j < 8; j++) {
                acc[j].x = fmaf(av4[j], w.x, acc[j].x);
                acc[j].y = fmaf(av4[j], w.y, acc[j].y);
                acc[j].z = fmaf(av4[j], w.z, acc[j].z);
                acc[j].w = fmaf(av4[j], w.w, acc[j].w);
            }
        }
    }
    float4 bi = *(const float4*)(b_in + cg * 4);
#pragma unroll
    for (int j = 0; j < 8; j++) {
        float4 v = acc[j];
        v.x += bi.x; v.y += bi.y; v.z += bi.z; v.w += bi.w;
        *(float4*)(g_p + (size_t)(row0 + r * 8 + j) * C_ + cg * 4) = v;
    }
}

// ---------------- pos projection + gather-add ----------------
__global__ __launch_bounds__(512) void posproj_kernel(
    const float* __restrict__ rel_pos, const float* __restrict__ W_pos,
    const float* __restrict__ b_pos)
{
    __shared__ float sA[32][68];
    __shared__ float sW[32][256];
    __shared__ float s_rel[64];
    __shared__ float s_freq[128];
    __shared__ int   s_id[64];
    int tid = threadIdx.x;
    int r = tid >> 6, cg = tid & 63;
    int b = blockIdx.y;
    int t0 = blockIdx.x * 64;
    int fA = tid >> 3, kqA = tid & 7;
    if (tid < 64) {
        s_rel[tid] = rel_pos[b * T_ + t0 + tid];
        s_id[tid]  = g_idx[b * T_ + t0 + tid];
    } else if (tid < 192) {
        int j = tid - 64;
        s_freq[j] = expf(-9.210340371976184f * (float)j * (1.0f / 127.0f));
    }
    __syncthreads();
    float4 acc[8];
#pragma unroll
    for (int j = 0; j < 8; j++) acc[j] = make_float4(0.f, 0.f, 0.f, 0.f);
    for (int kt = 0; kt < C_ / 32; kt++) {
        __syncthreads();
        float rv = s_rel[fA];
#pragma unroll
        for (int j = 0; j < 4; j++) {
            int k = kt * 32 + kqA * 4 + j;
            float arg = rv * s_freq[k & 127];
            sA[kqA * 4 + j][fA] = (k < 128) ? sinf(arg) : cosf(arg);
        }
#pragma unroll
        for (int q = 0; q < 4; q++) {
            int e = tid + q * 512;
            int kk = e >> 6, c4 = e & 63;
            *(float4*)&sW[kk][c4 * 4] = *(const float4*)(W_pos + (size_t)(kt * 32 + kk) * C_ + c4 * 4);
        }
        __syncthreads();
#pragma unroll
        for (int kk = 0; kk < 32; kk++) {
            float4 a0 = *(const float4*)&sA[kk][r * 8];
            float4 a1 = *(const float4*)&sA[kk][r * 8 + 4];
            float4 w  = *(const float4*)&sW[kk][cg * 4];
            float av4[8] = {a0.x,a0.y,a0.z,a0.w,a1.x,a1.y,a1.z,a1.w};
#pragma unroll
            for (int j = 0; j < 8; j++) {
                acc[j].x = fmaf(av4[j], w.x, acc[j].x);
                acc[j].y = fmaf(av4[j], w.y, acc[j].y);
                acc[j].z = fmaf(av4[j], w.z, acc[j].z);
                acc[j].w = fmaf(av4[j], w.w, acc[j].w);
            }
        }
    }
    float4 bp = *(const float4*)(b_pos + cg * 4);
#pragma unroll
    for (int j = 0; j < 8; j++) {
        int f = r * 8 + j;
        float4 pv = *(const float4*)(g_p + ((size_t)(b * N_ + s_id[f]) << 8) + cg * 4);
        float4 v = acc[j];
        v.x += bp.x + pv.x; v.y += bp.y + pv.y;
        v.z += bp.z + pv.z; v.w += bp.w + pv.w;
        *(float4*)(g_x + ((size_t)(b * T_ + t0 + f) << 8) + cg * 4) = v;
    }
}

// ---------------- prep: h0 = fp16(gelu(LN0(x))) ----------------
__device__ __forceinline__ float warp_sum(float v) {
#pragma unroll
    for (int off = 16; off; off >>= 1) v += __shfl_xor_sync(0xffffffffu, v, off);
    return v;
}
__global__ __launch_bounds__(256) void prep_kernel(
    const float* __restrict__ g0, const float* __restrict__ b0)
{
    int warp = threadIdx.x >> 5, lane = threadIdx.x & 31;
    int frame = blockIdx.x * 8 + warp;
    const float* xr = g_x + ((size_t)frame << 8);
    float v[8];
#pragma unroll
    for (int i = 0; i < 8; i++) v[i] = xr[lane + 32 * i];
    float s = 0.f;
#pragma unroll
    for (int i = 0; i < 8; i++) s += v[i];
    float mean = warp_sum(s) * (1.0f / C_);
    float s2 = 0.f;
#pragma unroll
    for (int i = 0; i < 8; i++) { float d = v[i] - mean; s2 += d * d; }
    float rstd = rsqrtf(warp_sum(s2) * (1.0f / C_) + EPS_);
#pragma unroll
    for (int i = 0; i < 8; i++) {
        int ch = lane + 32 * i;
        float y = (v[i] - mean) * rstd * g0[ch] + b0[ch];
        float gl = 0.5f * y * (1.0f + erff(y * 0.70710678118654752f));
        g_hA[((size_t)frame << 8) + ch] = __float2half_rn(gl);
    }
}

// ---------------- mma.sync conv layer (fp16 single-pass, K=64 steps) --------
// smem layout (dynamic):
//   A: 158 rows x 528B                 [0, 83424)
//   B: 2 stages x 36864B (256 rows x 144B)  [83424, 157152)
#define AROWB 528
#define B_OFF  83424
#define BROWB 144
#define BSTAGE 36864
#define DYN_SMEM 157184
#define NSTEP (K_ * 4)       // 124 (K=64 per step)
#define SB_STRIDE 268        // epilogue sbuf float stride

__device__ __forceinline__ void loadB(uint32_t dbase, int stage, int step, int l) {
    int tid = threadIdx.x;
    int kt = step >> 2, kc64 = step & 3;
    int z = l * K_ + kt;
    const __half* src = g_wh + (((size_t)(z * C_ + tid)) << 8) + kc64 * 64;
    uint32_t brow = dbase + B_OFF + (uint32_t)stage * BSTAGE + (uint32_t)tid * BROWB;
#pragma unroll
    for (int q = 0; q < 8; q++)
        cpa16(brow + q * 16, src + q * 8, 16);
}

__global__ __launch_bounds__(256, 1) void conv_mma_kernel(
    int l, int pp, int last,
    const float* __restrict__ conv_b,
    const float* __restrict__ ng, const float* __restrict__ nb,
    float* __restrict__ outp)
{
    extern __shared__ char dsm[];
    __shared__ float s_cb[C_], s_g[C_], s_b[C_];

    int tid = threadIdx.x;
    int wid = tid >> 5, lane = tid & 31;
    int warpM = wid >> 2, warpN = wid & 3;       // 2 x 4 warp grid
    int b  = blockIdx.x >> 6;
    int t0 = (blockIdx.x & 63) << 7;

    const __half* hh = pp ? g_hB : g_hA;
    __half* dsth = pp ? g_hA : g_hB;

    uint32_t dbase = smem_u32(dsm);

    if (tid < C_) {
        s_cb[tid] = conv_b[l * C_ + tid];
        s_g[tid]  = ng[tid];
        s_b[tid]  = nb[tid];
    }

    // ---- prologue: A window (158 rows) + B stages 0,1 ----
    for (int e = tid; e < 158 * 32; e += 256) {
        int r = e >> 5, g = e & 31;
        int t = t0 - (K_ - 1) + r;
        int sz = (t >= 0) ? 16 : 0;
        size_t srow = (((size_t)(b * T_ + (t < 0 ? 0 : t))) << 8) + g * 8;
        cpa16(dbase + (uint32_t)r * AROWB + g * 16, hh + srow, sz);
    }
    loadB(dbase, 0, 0, l);
    CP_COMMIT();                 // group0 = A + B0
    loadB(dbase, 1, 1, l);
    CP_COMMIT();                 // group1 = B1

    float acc[4][8][4];
#pragma unroll
    for (int mi = 0; mi < 4; mi++)
#pragma unroll
        for (int ni = 0; ni < 8; ni++)
#pragma unroll
            for (int q = 0; q < 4; q++) acc[mi][ni][q] = 0.f;

    uint32_t bl_lane = (uint32_t)(((lane & 7) + ((lane >> 4) << 3)) * BROWB + (((lane >> 3) & 1) << 4));

    for (int i = 0; i < NSTEP; i++) {
        int s = i & 1;
        CP_WAIT1();
        __syncthreads();

        int kt = i >> 2, kc64 = i & 3;
        uint32_t bs = dbase + B_OFF + (uint32_t)s * BSTAGE;

#pragma unroll
        for (int j = 0; j < 4; j++) {
            int kc = kc64 * 4 + j;      // K16 index within C=256
            uint32_t abase = dbase
                + (uint32_t)(kt + warpM * 64 + (lane & 15)) * AROWB
                + (uint32_t)(kc * 16 + ((lane >> 4) << 3)) * 2;

            uint32_t ah[4][4];
#pragma unroll
            for (int mi = 0; mi < 4; mi++)
                ldsm4(ah[mi], abase + mi * 16 * AROWB);

            uint32_t bb[8][2];
#pragma unroll
            for (int nq = 0; nq < 4; nq++) {
                uint32_t r4[4];
                ldsm4(r4, bs + (uint32_t)(warpN * 64 + nq * 16) * BROWB + j * 32 + bl_lane);
                bb[nq * 2][0] = r4[0]; bb[nq * 2][1] = r4[1];
                bb[nq * 2 + 1][0] = r4[2]; bb[nq * 2 + 1][1] = r4[3];
            }
#pragma unroll
            for (int mi = 0; mi < 4; mi++)
#pragma unroll
                for (int ni = 0; ni < 8; ni++)
                    mma16816(acc[mi][ni], ah[mi], bb[ni]);
        }

        __syncthreads();
        if (i + 2 < NSTEP) loadB(dbase, s, i + 2, l);
        CP_COMMIT();
    }
    __syncthreads();

    // ---- epilogue: acc -> smem (aliases A region), then fused LN ----
    float* sbuf = (float*)dsm;   // [128][SB_STRIDE]
#pragma unroll
    for (int mi = 0; mi < 4; mi++)
#pragma unroll
        for (int ni = 0; ni < 8; ni++) {
            int r0 = warpM * 64 + mi * 16 + (lane >> 2);
            int col = warpN * 64 + ni * 8 + ((lane & 3) << 1);
            *(float2*)&sbuf[r0 * SB_STRIDE + col] =
                make_float2(acc[mi][ni][0], acc[mi][ni][1]);
            *(float2*)&sbuf[(r0 + 8) * SB_STRIDE + col] =
                make_float2(acc[mi][ni][2], acc[mi][ni][3]);
        }
    __syncthreads();

    for (int f0 = 0; f0 < 16; f0++) {
        int f = wid * 16 + f0;
        size_t rowid = ((size_t)(b * T_ + t0 + f)) << 8;
        int c0 = lane * 8;
        float4 u0 = *(float4*)&sbuf[f * SB_STRIDE + c0];
        float4 u1 = *(float4*)&sbuf[f * SB_STRIDE + c0 + 4];
        float4 x0 = *(const float4*)(g_x + rowid + c0);
        float4 x1 = *(const float4*)(g_x + rowid + c0 + 4);
        float y[8];
        y[0] = u0.x + x0.x + s_cb[c0 + 0]; y[1] = u0.y + x0.y + s_cb[c0 + 1];
        y[2] = u0.z + x0.z + s_cb[c0 + 2]; y[3] = u0.w + x0.w + s_cb[c0 + 3];
        y[4] = u1.x + x1.x + s_cb[c0 + 4]; y[5] = u1.y + x1.y + s_cb[c0 + 5];
        y[6] = u1.z + x1.z + s_cb[c0 + 6]; y[7] = u1.w + x1.w + s_cb[c0 + 7];
        float sum = 0.f, sq = 0.f;
#pragma unroll
        for (int j = 0; j < 8; j++) { sum += y[j]; sq += y[j] * y[j]; }
        float mu = warp_sum(sum) * (1.f / C_);
        float rs = rsqrtf(warp_sum(sq) * (1.f / C_) - mu * mu + EPS_);
        float z[8];
#pragma unroll
        for (int j = 0; j < 8; j++)
            z[j] = (y[j] - mu) * rs * s_g[c0 + j] + s_b[c0 + j];
        if (last) {
            float4 o0 = {z[0], z[1], z[2], z[3]};
            float4 o1 = {z[4], z[5], z[6], z[7]};
            *(float4*)(outp + rowid + c0)     = o0;
            *(float4*)(outp + rowid + c0 + 4) = o1;
        } else {
            float4 y0 = {y[0], y[1], y[2], y[3]};
            float4 y1 = {y[4], y[5], y[6], y[7]};
            *(float4*)(g_x + rowid + c0)     = y0;
            *(float4*)(g_x + rowid + c0 + 4) = y1;
            __half hv[8];
#pragma unroll
            for (int j = 0; j < 8; j++) {
                float gl = 0.5f * z[j] * (1.0f + erff(z[j] * 0.70710678118654752f));
                hv[j] = __float2half_rn(gl);
            }
#pragma unroll
            for (int j = 0; j < 4; j++) {
                __half2 h2 = {hv[2 * j], hv[2 * j + 1]};
                *(__half2*)(dsth + rowid + c0 + 2 * j) = h2;
            }
        }
    }
}

// ---------------------------------------------------------------------------
extern "C" void kernel_launch(void* const* d_in, const int* in_sizes, int n_in,
                              void* d_out, int out_size)
{
    const float* pooled    = (const float*)d_in[0];
    const int*   durations = (const int*)  d_in[1];
    const float* rel_pos   = (const float*)d_in[2];
    const float* W_in      = (const float*)d_in[3];
    const float* b_in      = (const float*)d_in[4];
    const float* W_pos     = (const float*)d_in[5];
    const float* b_pos     = (const float*)d_in[6];
    const float* ln_g      = (const float*)d_in[7];
    const float* ln_b      = (const float*)d_in[8];
    const float* conv_w    = (const float*)d_in[9];
    const float* conv_b    = (const float*)d_in[10];
    const float* out_g     = (const float*)d_in[11];
    const float* out_b     = (const float*)d_in[12];
    float* out = (float*)d_out;

    cudaFuncSetAttribute(conv_mma_kernel,
                         cudaFuncAttributeMaxDynamicSharedMemorySize, DYN_SMEM);

    idx_kernel<<<B_, 256>>>(durations);
    wsplit_kernel<<<NZ * C_, 256>>>(conv_w);
    phoneme_proj_kernel<<<B_ * N_ / 64, 512>>>(pooled, W_in, b_in);
    posproj_kernel<<<dim3(T_ / 64, B_), 512>>>(rel_pos, W_pos, b_pos);
    prep_kernel<<<B_ * T_ / 8, 256>>>(ln_g, ln_b);

    conv_mma_kernel<<<B_ * T_ / 128, 256, DYN_SMEM>>>(
        0, 0, 0, conv_b, ln_g + C_, ln_b + C_, out);
    conv_mma_kernel<<<B_ * T_ / 128, 256, DYN_SMEM>>>(
        1, 1, 0, conv_b, ln_g + 2 * C_, ln_b + 2 * C_, out);
    conv_mma_kernel<<<B_ * T_ / 128, 256, DYN_SMEM>>>(
        2, 0, 1, conv_b, out_g, out_b, out);
}

// round 17
// speedup vs baseline: 47.7877x; 1.0148x over previous
#include <cuda_runtime.h>
#include <cuda_fp16.h>
#include <cstdint>
#include <stdint.h>
#include <math.h>

#define B_ 8
#define N_ 1024
#define DIN 512
#define C_ 256
#define T_ 8192
#define K_ 31
#define L_ 3
#define EPS_ 1e-5f
#define NZ (L_ * K_)

// device scratch (allocation-free rule)
__device__ __align__(1024) float g_x[B_ * T_ * C_];
__device__ __align__(1024) float g_p[B_ * N_ * C_];
__device__ __align__(1024) __half g_hA[B_ * T_ * C_];
__device__ __align__(1024) __half g_hB[B_ * T_ * C_];
__device__ __align__(1024) __half g_wh[NZ * C_ * C_];
__device__ int g_idx[B_ * T_];

// ---------------- PTX helpers ----------------
__device__ __forceinline__ uint32_t smem_u32(const void* p) {
    uint32_t a;
    asm("{ .reg .u64 t; cvta.to.shared.u64 t, %1; cvt.u32.u64 %0, t; }" : "=r"(a) : "l"(p));
    return a;
}
__device__ __forceinline__ void cpa16(uint32_t dst, const void* src, int sz) {
    asm volatile("cp.async.cg.shared.global [%0], [%1], 16, %2;"
                 :: "r"(dst), "l"(src), "r"(sz) : "memory");
}
#define CP_COMMIT() asm volatile("cp.async.commit_group;" ::: "memory")
#define CP_WAIT1()  asm volatile("cp.async.wait_group 1;" ::: "memory")

__device__ __forceinline__ void ldsm4(uint32_t* r, uint32_t a) {
    asm volatile("ldmatrix.sync.aligned.m8n8.x4.shared.b16 {%0,%1,%2,%3}, [%4];"
        : "=r"(r[0]), "=r"(r[1]), "=r"(r[2]), "=r"(r[3]) : "r"(a));
}
__device__ __forceinline__ void mma16816(float* c, const uint32_t* a, const uint32_t* b) {
    asm volatile("mma.sync.aligned.m16n8k16.row.col.f32.f16.f16.f32 "
        "{%0,%1,%2,%3}, {%4,%5,%6,%7}, {%8,%9}, {%0,%1,%2,%3};"
        : "+f"(c[0]), "+f"(c[1]), "+f"(c[2]), "+f"(c[3])
        : "r"(a[0]), "r"(a[1]), "r"(a[2]), "r"(a[3]), "r"(b[0]), "r"(b[1]));
}

__device__ __forceinline__ float warp_sum(float v) {
#pragma unroll
    for (int off = 16; off; off >>= 1) v += __shfl_xor_sync(0xffffffffu, v, off);
    return v;
}

// ---------------- idx kernel ----------------
__global__ __launch_bounds__(256) void idx_kernel(const int* __restrict__ durations) {
    __shared__ int cum[N_];
    __shared__ int wsum[8];
    int b = blockIdx.x, tid = threadIdx.x;
    int lane = tid & 31, warp = tid >> 5;
    int d[4], inc[4];
    int s = 0;
#pragma unroll
    for (int i = 0; i < 4; i++) { d[i] = durations[b * N_ + tid * 4 + i]; s += d[i]; inc[i] = s; }
    int x = s;
#pragma unroll
    for (int off = 1; off < 32; off <<= 1) {
        int y = __shfl_up_sync(0xffffffffu, x, off);
        if (lane >= off) x += y;
    }
    if (lane == 31) wsum[warp] = x;
    __syncthreads();
    if (tid == 0) {
        int acc = 0;
#pragma unroll
        for (int w = 0; w < 8; w++) { int v = wsum[w]; wsum[w] = acc; acc += v; }
    }
    __syncthreads();
    int excl = wsum[warp] + (x - s);
#pragma unroll
    for (int i = 0; i < 4; i++) cum[tid * 4 + i] = excl + inc[i];
    __syncthreads();
    for (int t = tid; t < T_; t += 256) {
        int lo = 0, hi = N_ - 1;
        while (lo < hi) { int m = (lo + hi) >> 1; if (cum[m] > t) hi = m; else lo = m + 1; }
        g_idx[b * T_ + t] = lo;
    }
}

// ---------------- weights: conv_w[l][o][i][k] -> fp16 [z][o][i] -------------
__global__ __launch_bounds__(256) void wsplit_kernel(const float* __restrict__ cw) {
    int blk = blockIdx.x;                 // z*256 + o
    int o = blk & 255, z = blk >> 8;
    int l = z / K_, k = z - l * K_;
    int i = threadIdx.x;
    float w = cw[((size_t)((l * C_ + o) * C_ + i)) * K_ + k];
    g_wh[((size_t)z * C_ + o) * C_ + i] = __float2half_rn(w);
}

// ---------------- phoneme projection GEMM ----------------
__global__ __launch_bounds__(512) void phoneme_proj_kernel(
    const float* __restrict__ pooled, const float* __restrict__ W_in,
    const float* __restrict__ b_in)
{
    __shared__ float sA[32][68];
    __shared__ float sW[32][256];
    int tid = threadIdx.x;
    int r = tid >> 6, cg = tid & 63;
    int row0 = blockIdx.x * 64;
    int fA = tid >> 3, kqA = tid & 7;
    float4 acc[8];
#pragma unroll
    for (int j = 0; j < 8; j++) acc[j] = make_float4(0.f, 0.f, 0.f, 0.f);
    for (int kt = 0; kt < DIN / 32; kt++) {
        __syncthreads();
        float4 av = *(const float4*)(pooled + (size_t)(row0 + fA) * DIN + kt * 32 + kqA * 4);
        sA[kqA * 4 + 0][fA] = av.x; sA[kqA * 4 + 1][fA] = av.y;
        sA[kqA * 4 + 2][fA] = av.z; sA[kqA * 4 + 3][fA] = av.w;
#pragma unroll
        for (int q = 0; q < 4; q++) {
            int e = tid + q * 512;
            int kk = e >> 6, c4 = e & 63;
            *(float4*)&sW[kk][c4 * 4] = *(const float4*)(W_in + (size_t)(kt * 32 + kk) * C_ + c4 * 4);
        }
        __syncthreads();
#pragma unroll
        for (int kk = 0; kk < 32; kk++) {
            float4 a0 = *(const float4*)&sA[kk][r * 8];
            float4 a1 = *(const float4*)&sA[kk][r * 8 + 4];
            float4 w  = *(const float4*)&sW[kk][cg * 4];
            float av4[8] = {a0.x,a0.y,a0.z,a0.w,a1.x,a1.y,a1.z,a1.w};
#pragma unroll
            for (int j = 0; j < 8; j++) {
                acc[j].x = fmaf(av4[j], w.x, acc[j].x);
                acc[j].y = fmaf(av4[j], w.y, acc[j].y);
                acc[j].z = fmaf(av4[j], w.z, acc[j].z);
                acc[j].w = fmaf(av4[j], w.w, acc[j].w);
            }
        }
    }
    float4 bi = *(const float4*)(b_in + cg * 4);
#pragma unroll
    for (int j = 0; j < 8; j++) {
        float4 v = acc[j];
        v.x += bi.x; v.y += bi.y; v.z += bi.z; v.w += bi.w;
        *(float4*)(g_p + (size_t)(row0 + r * 8 + j) * C_ + cg * 4) = v;
    }
}

// ---------------- pos projection + gather-add + fused LN0/GELU -> g_hA ------
__global__ __launch_bounds__(512) void posproj_kernel(
    const float* __restrict__ rel_pos, const float* __restrict__ W_pos,
    const float* __restrict__ b_pos,
    const float* __restrict__ ln_g0, const float* __restrict__ ln_b0)
{
    __shared__ float sA[32][68];
    __shared__ float sW[32][256];
    __shared__ float s_rel[64];
    __shared__ float s_freq[128];
    __shared__ int   s_id[64];
    __shared__ float red_s[8][8][2], red_q[8][8][2];
    int tid = threadIdx.x;
    int r = tid >> 6, cg = tid & 63;
    int lane = tid & 31, half = (tid >> 5) & 1;
    int b = blockIdx.y;
    int t0 = blockIdx.x * 64;
    int fA = tid >> 3, kqA = tid & 7;
    if (tid < 64) {
        s_rel[tid] = rel_pos[b * T_ + t0 + tid];
        s_id[tid]  = g_idx[b * T_ + t0 + tid];
    } else if (tid < 192) {
        int j = tid - 64;
        s_freq[j] = expf(-9.210340371976184f * (float)j * (1.0f / 127.0f));
    }
    __syncthreads();
    float4 acc[8];
#pragma unroll
    for (int j = 0; j < 8; j++) acc[j] = make_float4(0.f, 0.f, 0.f, 0.f);
    for (int kt = 0; kt < C_ / 32; kt++) {
        __syncthreads();
        float rv = s_rel[fA];
#pragma unroll
        for (int j = 0; j < 4; j++) {
            int k = kt * 32 + kqA * 4 + j;
            float arg = rv * s_freq[k & 127];
            sA[kqA * 4 + j][fA] = (k < 128) ? sinf(arg) : cosf(arg);
        }
#pragma unroll
        for (int q = 0; q < 4; q++) {
            int e = tid + q * 512;
            int kk = e >> 6, c4 = e & 63;
            *(float4*)&sW[kk][c4 * 4] = *(const float4*)(W_pos + (size_t)(kt * 32 + kk) * C_ + c4 * 4);
        }
        __syncthreads();
#pragma unroll
        for (int kk = 0; kk < 32; kk++) {
            float4 a0 = *(const float4*)&sA[kk][r * 8];
            float4 a1 = *(const float4*)&sA[kk][r * 8 + 4];
            float4 w  = *(const float4*)&sW[kk][cg * 4];
            float av4[8] = {a0.x,a0.y,a0.z,a0.w,a1.x,a1.y,a1.z,a1.w};
#pragma unroll
            for (int j = 0; j < 8; j++) {
                acc[j].x = fmaf(av4[j], w.x, acc[j].x);
                acc[j].y = fmaf(av4[j], w.y, acc[j].y);
                acc[j].z = fmaf(av4[j], w.z, acc[j].z);
                acc[j].w = fmaf(av4[j], w.w, acc[j].w);
            }
        }
    }
    float4 bp = *(const float4*)(b_pos + cg * 4);
#pragma unroll
    for (int j = 0; j < 8; j++) {
        int f = r * 8 + j;
        float4 pv = *(const float4*)(g_p + ((size_t)(b * N_ + s_id[f]) << 8) + cg * 4);
        float4 v = acc[j];
        v.x += bp.x + pv.x; v.y += bp.y + pv.y;
        v.z += bp.z + pv.z; v.w += bp.w + pv.w;
        *(float4*)(g_x + ((size_t)(b * T_ + t0 + f) << 8) + cg * 4) = v;
        acc[j] = v;
        float s = v.x + v.y + v.z + v.w;
        float q = v.x * v.x + v.y * v.y + v.z * v.z + v.w * v.w;
        s = warp_sum(s);
        q = warp_sum(q);
        if (lane == 0) { red_s[r][j][half] = s; red_q[r][j][half] = q; }
    }
    __syncthreads();
    float4 gv = *(const float4*)(ln_g0 + cg * 4);
    float4 bv = *(const float4*)(ln_b0 + cg * 4);
#pragma unroll
    for (int j = 0; j < 8; j++) {
        float mu = (red_s[r][j][0] + red_s[r][j][1]) * (1.0f / C_);
        float var = (red_q[r][j][0] + red_q[r][j][1]) * (1.0f / C_) - mu * mu;
        float rs = rsqrtf(var + EPS_);
        float4 v = acc[j];
        float z0 = (v.x - mu) * rs * gv.x + bv.x;
        float z1 = (v.y - mu) * rs * gv.y + bv.y;
        float z2 = (v.z - mu) * rs * gv.z + bv.z;
        float z3 = (v.w - mu) * rs * gv.w + bv.w;
        float g0 = 0.5f * z0 * (1.0f + erff(z0 * 0.70710678118654752f));
        float g1 = 0.5f * z1 * (1.0f + erff(z1 * 0.70710678118654752f));
        float g2 = 0.5f * z2 * (1.0f + erff(z2 * 0.70710678118654752f));
        float g3 = 0.5f * z3 * (1.0f + erff(z3 * 0.70710678118654752f));
        size_t rowh = ((size_t)(b * T_ + t0 + r * 8 + j) << 8) + cg * 4;
        __half2 h0 = {__float2half_rn(g0), __float2half_rn(g1)};
        __half2 h1 = {__float2half_rn(g2), __float2half_rn(g3)};
        *(__half2*)(g_hA + rowh)     = h0;
        *(__half2*)(g_hA + rowh + 2) = h1;
    }
}

// ---------------- mma.sync conv layer (fp16 single-pass, 3-stage, 1 sync) ---
// smem layout (dynamic):
//   A: 158 rows x 528B                      [0, 83424)
//   B: 3 stages x 36864B (256 rows x 144B)  [83424, 194016)
#define AROWB 528
#define B_OFF  83424
#define BROWB 144
#define BSTAGE 36864
#define DYN_SMEM 194048
#define NSTEP (K_ * 4)       // 124 (K=64 per step)
#define SB_STRIDE 268        // epilogue sbuf float stride

__device__ __forceinline__ void loadB(uint32_t dbase, int buf, int step, int l) {
    int tid = threadIdx.x;
    int kt = step >> 2, kc64 = step & 3;
    int z = l * K_ + kt;
    const __half* src = g_wh + (((size_t)(z * C_ + tid)) << 8) + kc64 * 64;
    uint32_t brow = dbase + B_OFF + (uint32_t)buf * BSTAGE + (uint32_t)tid * BROWB;
#pragma unroll
    for (int q = 0; q < 8; q++)
        cpa16(brow + q * 16, src + q * 8, 16);
}

__global__ __launch_bounds__(256, 1) void conv_mma_kernel(
    int l, int pp, int last,
    const float* __restrict__ conv_b,
    const float* __restrict__ ng, const float* __restrict__ nb,
    float* __restrict__ outp)
{
    extern __shared__ char dsm[];
    __shared__ float s_cb[C_], s_g[C_], s_b[C_];

    int tid = threadIdx.x;
    int wid = tid >> 5, lane = tid & 31;
    int warpM = wid >> 2, warpN = wid & 3;       // 2 x 4 warp grid
    int b  = blockIdx.x >> 6;
    int t0 = (blockIdx.x & 63) << 7;

    const __half* hh = pp ? g_hB : g_hA;
    __half* dsth = pp ? g_hA : g_hB;

    uint32_t dbase = smem_u32(dsm);

    if (tid < C_) {
        s_cb[tid] = conv_b[l * C_ + tid];
        s_g[tid]  = ng[tid];
        s_b[tid]  = nb[tid];
    }

    // ---- prologue: A window (158 rows) + B steps 0,1 ----
    for (int e = tid; e < 158 * 32; e += 256) {
        int r = e >> 5, g = e & 31;
        int t = t0 - (K_ - 1) + r;
        int sz = (t >= 0) ? 16 : 0;
        size_t srow = (((size_t)(b * T_ + (t < 0 ? 0 : t))) << 8) + g * 8;
        cpa16(dbase + (uint32_t)r * AROWB + g * 16, hh + srow, sz);
    }
    loadB(dbase, 0, 0, l);
    CP_COMMIT();                 // group: A + B0
    loadB(dbase, 1, 1, l);
    CP_COMMIT();                 // group: B1

    float acc[4][8][4];
#pragma unroll
    for (int mi = 0; mi < 4; mi++)
#pragma unroll
        for (int ni = 0; ni < 8; ni++)
#pragma unroll
            for (int q = 0; q < 4; q++) acc[mi][ni][q] = 0.f;

    uint32_t bl_lane = (uint32_t)(((lane & 7) + ((lane >> 4) << 3)) * BROWB + (((lane >> 3) & 1) << 4));

    for (int i = 0; i < NSTEP; i++) {
        CP_WAIT1();              // this thread's step-i group landed
        __syncthreads();         // all threads waited -> data visible; iter i-1 consumption done

        int kt = i >> 2, kc64 = i & 3;
        uint32_t bs = dbase + B_OFF + (uint32_t)(i % 3) * BSTAGE;

#pragma unroll
        for (int j = 0; j < 4; j++) {
            int kc = kc64 * 4 + j;      // K16 index within C=256
            uint32_t abase = dbase
                + (uint32_t)(kt + warpM * 64 + (lane & 15)) * AROWB
                + (uint32_t)(kc * 16 + ((lane >> 4) << 3)) * 2;

            uint32_t ah[4][4];
#pragma unroll
            for (int mi = 0; mi < 4; mi++)
                ldsm4(ah[mi], abase + mi * 16 * AROWB);

            uint32_t bb[8][2];
#pragma unroll
            for (int nq = 0; nq < 4; nq++) {
                uint32_t r4[4];
                ldsm4(r4, bs + (uint32_t)(warpN * 64 + nq * 16) * BROWB + j * 32 + bl_lane);
                bb[nq * 2][0] = r4[0]; bb[nq * 2][1] = r4[1];
                bb[nq * 2 + 1][0] = r4[2]; bb[nq * 2 + 1][1] = r4[3];
            }
#pragma unroll
            for (int mi = 0; mi < 4; mi++)
#pragma unroll
                for (int ni = 0; ni < 8; ni++)
                    mma16816(acc[mi][ni], ah[mi], bb[ni]);
        }

        // prefetch step i+2 into buffer (i+2)%3 (consumed at iter i-1; safe after sync)
        if (i + 2 < NSTEP) loadB(dbase, (i + 2) % 3, i + 2, l);
        CP_COMMIT();
    }
    __syncthreads();

    // ---- epilogue: acc -> smem (aliases A region), then fused LN ----
    float* sbuf = (float*)dsm;   // [128][SB_STRIDE]
#pragma unroll
    for (int mi = 0; mi < 4; mi++)
#pragma unroll
        for (int ni = 0; ni < 8; ni++) {
            int r0 = warpM * 64 + mi * 16 + (lane >> 2);
            int col = warpN * 64 + ni * 8 + ((lane & 3) << 1);
            *(float2*)&sbuf[r0 * SB_STRIDE + col] =
                make_float2(acc[mi][ni][0], acc[mi][ni][1]);
            *(float2*)&sbuf[(r0 + 8) * SB_STRIDE + col] =
                make_float2(acc[mi][ni][2], acc[mi][ni][3]);
        }
    __syncthreads();

    for (int f0 = 0; f0 < 16; f0++) {
        int f = wid * 16 + f0;
        size_t rowid = ((size_t)(b * T_ + t0 + f)) << 8;
        int c0 = lane * 8;
        float4 u0 = *(float4*)&sbuf[f * SB_STRIDE + c0];
        float4 u1 = *(float4*)&sbuf[f * SB_STRIDE + c0 + 4];
        float4 x0 = *(const float4*)(g_x + rowid + c0);
        float4 x1 = *(const float4*)(g_x + rowid + c0 + 4);
        float y[8];
        y[0] = u0.x + x0.x + s_cb[c0 + 0]; y[1] = u0.y + x0.y + s_cb[c0 + 1];
        y[2] = u0.z + x0.z + s_cb[c0 + 2]; y[3] = u0.w + x0.w + s_cb[c0 + 3];
        y[4] = u1.x + x1.x + s_cb[c0 + 4]; y[5] = u1.y + x1.y + s_cb[c0 + 5];
        y[6] = u1.z + x1.z + s_cb[c0 + 6]; y[7] = u1.w + x1.w + s_cb[c0 + 7];
        float sum = 0.f, sq = 0.f;
#pragma unroll
        for (int j = 0; j < 8; j++) { sum += y[j]; sq += y[j] * y[j]; }
        float mu = warp_sum(sum) * (1.f / C_);
        float rs = rsqrtf(warp_sum(sq) * (1.f / C_) - mu * mu + EPS_);
        float z[8];
#pragma unroll
        for (int j = 0; j < 8; j++)
            z[j] = (y[j] - mu) * rs * s_g[c0 + j] + s_b[c0 + j];
        if (last) {
            float4 o0 = {z[0], z[1], z[2], z[3]};
            float4 o1 = {z[4], z[5], z[6], z[7]};
            *(float4*)(outp + rowid + c0)     = o0;
            *(float4*)(outp + rowid + c0 + 4) = o1;
        } else {
            float4 y0 = {y[0], y[1], y[2], y[3]};
            float4 y1 = {y[4], y[5], y[6], y[7]};
            *(float4*)(g_x + rowid + c0)     = y0;
            *(float4*)(g_x + rowid + c0 + 4) = y1;
            __half hv[8];
#pragma unroll
            for (int j = 0; j < 8; j++) {
                float gl = 0.5f * z[j] * (1.0f + erff(z[j] * 0.70710678118654752f));
                hv[j] = __float2half_rn(gl);
            }
#pragma unroll
            for (int j = 0; j < 4; j++) {
                __half2 h2 = {hv[2 * j], hv[2 * j + 1]};
                *(__half2*)(dsth + rowid + c0 + 2 * j) = h2;
            }
        }
    }
}

// ---------------------------------------------------------------------------
extern "C" void kernel_launch(void* const* d_in, const int* in_sizes, int n_in,
                              void* d_out, int out_size)
{
    const float* pooled    = (const float*)d_in[0];
    const int*   durations = (const int*)  d_in[1];
    const float* rel_pos   = (const float*)d_in[2];
    const float* W_in      = (const float*)d_in[3];
    const float* b_in      = (const float*)d_in[4];
    const float* W_pos     = (const float*)d_in[5];
    const float* b_pos     = (const float*)d_in[6];
    const float* ln_g      = (const float*)d_in[7];
    const float* ln_b      = (const float*)d_in[8];
    const float* conv_w    = (const float*)d_in[9];
    const float* conv_b    = (const float*)d_in[10];
    const float* out_g     = (const float*)d_in[11];
    const float* out_b     = (const float*)d_in[12];
    float* out = (float*)d_out;

    cudaFuncSetAttribute(conv_mma_kernel,
                         cudaFuncAttributeMaxDynamicSharedMemorySize, DYN_SMEM);

    idx_kernel<<<B_, 256>>>(durations);
    wsplit_kernel<<<NZ * C_, 256>>>(conv_w);
    phoneme_proj_kernel<<<B_ * N_ / 64, 512>>>(pooled, W_in, b_in);
    posproj_kernel<<<dim3(T_ / 64, B_), 512>>>(rel_pos, W_pos, b_pos, ln_g, ln_b);

    conv_mma_kernel<<<B_ * T_ / 128, 256, DYN_SMEM>>>(
        0, 0, 0, conv_b, ln_g + C_, ln_b + C_, out);
    conv_mma_kernel<<<B_ * T_ / 128, 256, DYN_SMEM>>>(
        1, 1, 0, conv_b, ln_g + 2 * C_, ln_b + 2 * C_, out);
    conv_mma_kernel<<<B_ * T_ / 128, 256, DYN_SMEM>>>(
        2, 0, 1, conv_b, out_g, out_b, out);
}